// round 5
// baseline (speedup 1.0000x reference)
#include <cuda_runtime.h>
#include <math.h>

// Problem dims (fixed by the reference)
constexpr int B_   = 64;
constexpr int S_   = 512;
constexpr int D_   = 256;
constexpr int H_   = 8;
constexpr int DK_  = 32;
constexpr int DFF_ = 1024;
constexpr int BS_  = B_ * S_;          // 32768 rows
constexpr float SCALE_ = 0.17677669529663687f; // 1/sqrt(32)

// ---------------------------------------------------------------------------
// Scratch (no allocations allowed -> __device__ globals)
// ---------------------------------------------------------------------------
__device__ float g_y  [BS_ * D_];
__device__ float g_x  [BS_ * D_];
__device__ float g_kp [BS_ * D_];
__device__ float g_vp [BS_ * D_];
__device__ float g_att[BS_ * D_];
__device__ float g_o  [BS_ * D_];
__device__ float g_x1 [BS_ * D_];
__device__ float g_f  [BS_ * D_];
__device__ float g_h  [BS_ * DFF_];

// ---------------------------------------------------------------------------
// tf32 helpers
// ---------------------------------------------------------------------------
__device__ __forceinline__ float f2tf32(float x) {
    unsigned r;
    asm("cvt.rna.tf32.f32 %0, %1;" : "=r"(r) : "f"(x));
    return __uint_as_float(r);
}

__device__ __forceinline__ void mma_tf32(
    float& c0, float& c1, float& c2, float& c3,
    unsigned a0, unsigned a1, unsigned a2, unsigned a3,
    unsigned b0, unsigned b1)
{
    asm volatile(
        "mma.sync.aligned.m16n8k8.row.col.f32.tf32.tf32.f32 "
        "{%0,%1,%2,%3}, {%4,%5,%6,%7}, {%8,%9}, {%0,%1,%2,%3};\n"
        : "+f"(c0), "+f"(c1), "+f"(c2), "+f"(c3)
        : "r"(a0), "r"(a1), "r"(a2), "r"(a3), "r"(b0), "r"(b1));
}

// ---------------------------------------------------------------------------
// Tensor-core GEMM (tf32), double-buffered, FRAGMENT-MAJOR smem layout.
// Block 128x128, BK=16, 256 threads = 8 warps, warp tile 64x32.
// A frag slot:  idx = ((kstep*8  + mtg)*32 + sA)*4 + (kh*2+mh), sA = t4*8+g
// B frag slot:  idx = ((kstep*16 + ntg)*32 + sB)*2 + kh,        sB = t4*8+g
// Consumer: 1x LDS.128 per A-frag, 1x LDS.64 per B-frag (conflict-free).
// Dual-GEMM: blockIdx.z selects operand set (merges K/V projections).
// ---------------------------------------------------------------------------
constexpr int FSTG = 2048;   // floats per operand per stage

__global__ __launch_bounds__(256, 2) void gemm_tc(
    const float* __restrict__ A0, const float* __restrict__ W0,
    const float* __restrict__ bias0, float* __restrict__ C0,
    const float* __restrict__ A1, const float* __restrict__ W1p,
    const float* __restrict__ bias1, float* __restrict__ C1,
    int M, int N, int K, int relu)
{
    __shared__ float Af[2 * FSTG];
    __shared__ float Bf[2 * FSTG];

    const float* A    = blockIdx.z ? A1    : A0;
    const float* W    = blockIdx.z ? W1p   : W0;
    const float* bias = blockIdx.z ? bias1 : bias0;
    float*       C    = blockIdx.z ? C1    : C0;

    const int tid  = threadIdx.x;
    const int lane = tid & 31;
    const int warp = tid >> 5;
    const int wm   = warp >> 2;
    const int wn   = warp & 3;
    const int g    = lane >> 2;
    const int t4   = lane & 3;
    const int bm = blockIdx.y * 128;
    const int bn = blockIdx.x * 128;
    const int nk = K >> 4;

    // staging descriptors (constant across K-tiles)
    const float* aptr[2]; int aoff[2];
    const float* bptr[2]; int boff[2];
    #pragma unroll
    for (int i = 0; i < 2; i++) {
        const int f = tid + (i << 8);
        const int m  = f >> 2;
        const int kq = (f & 3) << 2;
        aptr[i] = A + (size_t)(bm + m) * K + kq;
        const int mtg = m >> 4, ga = m & 7, mh = (m >> 3) & 1;
        const int kstA = kq >> 3, khA = (kq >> 2) & 1;
        aoff[i] = (((kstA << 3) + mtg) * 32 + ga) * 4 + khA * 2 + mh;
        const int kk = f & 15;
        const int n  = (f >> 4) << 2;
        bptr[i] = W + (size_t)kk * N + bn + n;
        const int kstB = kk >> 3, khB = (kk >> 2) & 1, t4B = kk & 3;
        const int ntg = n >> 3, gb = n & 7;
        boff[i] = (((kstB << 4) + ntg) * 32 + t4B * 8 + gb) * 2 + khB;
    }

    float acc[4][4][4];
    #pragma unroll
    for (int mt = 0; mt < 4; mt++)
        #pragma unroll
        for (int nt = 0; nt < 4; nt++)
            #pragma unroll
            for (int i = 0; i < 4; i++) acc[mt][nt][i] = 0.f;

    // stage K-tile 0 into buffer 0
    #pragma unroll
    for (int i = 0; i < 2; i++) {
        const float4 va = *(const float4*)aptr[i];
        float* Ad = Af + aoff[i];
        Ad[0]  = f2tf32(va.x); Ad[32] = f2tf32(va.y);
        Ad[64] = f2tf32(va.z); Ad[96] = f2tf32(va.w);
        const float4 vb = *(const float4*)bptr[i];
        float* Bd = Bf + boff[i];
        Bd[0] = f2tf32(vb.x); Bd[2] = f2tf32(vb.y);
        Bd[4] = f2tf32(vb.z); Bd[6] = f2tf32(vb.w);
    }
    __syncthreads();

    const int sl = (lane & 3) * 8 + (lane >> 2);   // permuted slot id
    // warp-fixed base offsets (floats)
    const int awbase = (wm * 4 * 32 + sl) * 4;      // + kstep*1024 + mt*128
    const int bwbase = (wn * 4 * 32 + sl) * 2;      // + kstep*1024 + nt*64

    for (int kt = 0; kt < nk; kt++) {
        const int cur = kt & 1;
        const bool pf = (kt + 1 < nk);
        float4 av[2], bv[2];
        if (pf) {
            #pragma unroll
            for (int i = 0; i < 2; i++) {
                av[i] = *(const float4*)(aptr[i] + (kt + 1) * 16);
                bv[i] = *(const float4*)(bptr[i] + (size_t)(kt + 1) * 16 * N);
            }
        }

        const float* Ac = Af + cur * FSTG;
        const float* Bc = Bf + cur * FSTG;
        #pragma unroll
        for (int ks = 0; ks < 2; ks++) {
            float4 a4[4]; float2 b2[4];
            #pragma unroll
            for (int mt = 0; mt < 4; mt++)
                a4[mt] = *(const float4*)(Ac + awbase + ks * 1024 + mt * 128);
            #pragma unroll
            for (int nt = 0; nt < 4; nt++)
                b2[nt] = *(const float2*)(Bc + bwbase + ks * 1024 + nt * 64);
            #pragma unroll
            for (int mt = 0; mt < 4; mt++)
                #pragma unroll
                for (int nt = 0; nt < 4; nt++)
                    mma_tf32(acc[mt][nt][0], acc[mt][nt][1],
                             acc[mt][nt][2], acc[mt][nt][3],
                             __float_as_uint(a4[mt].x), __float_as_uint(a4[mt].y),
                             __float_as_uint(a4[mt].z), __float_as_uint(a4[mt].w),
                             __float_as_uint(b2[nt].x), __float_as_uint(b2[nt].y));
        }

        if (pf) {
            float* An = Af + (cur ^ 1) * FSTG;
            float* Bn = Bf + (cur ^ 1) * FSTG;
            #pragma unroll
            for (int i = 0; i < 2; i++) {
                float* Ad = An + aoff[i];
                Ad[0]  = f2tf32(av[i].x); Ad[32] = f2tf32(av[i].y);
                Ad[64] = f2tf32(av[i].z); Ad[96] = f2tf32(av[i].w);
                float* Bd = Bn + boff[i];
                Bd[0] = f2tf32(bv[i].x); Bd[2] = f2tf32(bv[i].y);
                Bd[4] = f2tf32(bv[i].z); Bd[6] = f2tf32(bv[i].w);
            }
        }
        __syncthreads();
    }

    // epilogue: bias (+ReLU)
    #pragma unroll
    for (int mt = 0; mt < 4; mt++) {
        const int r = bm + wm * 64 + mt * 16 + g;
        #pragma unroll
        for (int nt = 0; nt < 4; nt++) {
            const int c = bn + wn * 32 + nt * 8 + 2 * t4;
            const float b0 = bias[c], b1 = bias[c + 1];
            float v0 = acc[mt][nt][0] + b0;
            float v1 = acc[mt][nt][1] + b1;
            float v2 = acc[mt][nt][2] + b0;
            float v3 = acc[mt][nt][3] + b1;
            if (relu) {
                v0 = fmaxf(v0, 0.f); v1 = fmaxf(v1, 0.f);
                v2 = fmaxf(v2, 0.f); v3 = fmaxf(v3, 0.f);
            }
            *(float2*)&C[(size_t)r * N + c]       = make_float2(v0, v1);
            *(float2*)&C[(size_t)(r + 8) * N + c] = make_float2(v2, v3);
        }
    }
}

// ---------------------------------------------------------------------------
// Tensor-core flash attention: q-tile 128, warp owns 16 rows x ALL 64 kv.
// Softmax in registers (quad shuffles); P relayout via warp-private smem rows.
// ---------------------------------------------------------------------------
constexpr int SS_STR = 68;
constexpr int KS_STR = 36;
constexpr int VS_STR = 40;
constexpr int SS_OFF = 0;
constexpr int KS_OFF = 128 * SS_STR;
constexpr int VS_OFF = KS_OFF + 64 * KS_STR;
constexpr int ATTN_SMEM_BYTES = (VS_OFF + 64 * VS_STR) * 4;  // 54272

__global__ __launch_bounds__(256) void attn_tc(
    const float* __restrict__ QK, const float* __restrict__ Vp,
    float* __restrict__ O, int strict)
{
    extern __shared__ float sm[];
    float* Ssm = sm + SS_OFF;
    float* Ksm = sm + KS_OFF;
    float* Vsm = sm + VS_OFF;

    const int qt = blockIdx.x;
    const int bh = blockIdx.y;
    const int b  = bh >> 3;
    const int h  = bh & 7;
    const int q0 = qt << 7;
    const int t    = threadIdx.x;
    const int lane = t & 31;
    const int warp = t >> 5;
    const int m0   = warp << 4;
    const int g    = lane >> 2;
    const int t4   = lane & 3;

    const size_t base = (size_t)(b * S_) * D_ + h * DK_;

    for (int i = t; i < 1024; i += 256) {
        const int r = i >> 3, c = (i & 7) << 2;
        float4 v = *(const float4*)&QK[base + (size_t)(q0 + r) * D_ + c];
        Ssm[r * SS_STR + c + 0] = f2tf32(v.x);
        Ssm[r * SS_STR + c + 1] = f2tf32(v.y);
        Ssm[r * SS_STR + c + 2] = f2tf32(v.z);
        Ssm[r * SS_STR + c + 3] = f2tf32(v.w);
    }
    __syncthreads();
    unsigned qf[4][4];
    #pragma unroll
    for (int ks = 0; ks < 4; ks++) {
        const int k = ks * 8;
        qf[ks][0] = __float_as_uint(Ssm[(m0 + g) * SS_STR + k + t4]);
        qf[ks][1] = __float_as_uint(Ssm[(m0 + g + 8) * SS_STR + k + t4]);
        qf[ks][2] = __float_as_uint(Ssm[(m0 + g) * SS_STR + k + t4 + 4]);
        qf[ks][3] = __float_as_uint(Ssm[(m0 + g + 8) * SS_STR + k + t4 + 4]);
    }

    float acc_o[4][4];
    #pragma unroll
    for (int nt = 0; nt < 4; nt++)
        #pragma unroll
        for (int i = 0; i < 4; i++) acc_o[nt][i] = 0.f;
    float mrow[2] = { -1e30f, -1e30f };
    float lrow[2] = { 0.f, 0.f };

    const int rg  = q0 + m0 + g - strict;
    const int rg8 = rg + 8;
    const int ktmax = 2 * qt + 1;

    for (int kt = 0; kt <= ktmax; kt++) {
        const int k0 = kt << 6;
        __syncthreads();
        for (int i = t; i < 512; i += 256) {
            const int rr = i >> 3, c = (i & 7) << 2;
            float4 kv = *(const float4*)&QK[base + (size_t)(k0 + rr) * D_ + c];
            Ksm[rr * KS_STR + c + 0] = f2tf32(kv.x);
            Ksm[rr * KS_STR + c + 1] = f2tf32(kv.y);
            Ksm[rr * KS_STR + c + 2] = f2tf32(kv.z);
            Ksm[rr * KS_STR + c + 3] = f2tf32(kv.w);
            float4 vv = *(const float4*)&Vp[base + (size_t)(k0 + rr) * D_ + c];
            Vsm[rr * VS_STR + c + 0] = f2tf32(vv.x);
            Vsm[rr * VS_STR + c + 1] = f2tf32(vv.y);
            Vsm[rr * VS_STR + c + 2] = f2tf32(vv.z);
            Vsm[rr * VS_STR + c + 3] = f2tf32(vv.w);
        }
        __syncthreads();

        float s[8][4];
        #pragma unroll
        for (int nt = 0; nt < 8; nt++)
            #pragma unroll
            for (int i = 0; i < 4; i++) s[nt][i] = 0.f;
        #pragma unroll
        for (int ks = 0; ks < 4; ks++) {
            const int kb = ks * 8;
            #pragma unroll
            for (int nt = 0; nt < 8; nt++) {
                const float* Kp = &Ksm[(nt * 8 + g) * KS_STR + kb + t4];
                unsigned b0 = __float_as_uint(Kp[0]);
                unsigned b1 = __float_as_uint(Kp[4]);
                mma_tf32(s[nt][0], s[nt][1], s[nt][2], s[nt][3],
                         qf[ks][0], qf[ks][1], qf[ks][2], qf[ks][3], b0, b1);
            }
        }

        #pragma unroll
        for (int nt = 0; nt < 8; nt++) {
            const int c0c = k0 + nt * 8 + 2 * t4;
            const int c1c = c0c + 1;
            s[nt][0] = (c0c <= rg ) ? s[nt][0] * SCALE_ : -1e30f;
            s[nt][1] = (c1c <= rg ) ? s[nt][1] * SCALE_ : -1e30f;
            s[nt][2] = (c0c <= rg8) ? s[nt][2] * SCALE_ : -1e30f;
            s[nt][3] = (c1c <= rg8) ? s[nt][3] * SCALE_ : -1e30f;
        }

        float mx0 = -1e30f, mx1 = -1e30f;
        #pragma unroll
        for (int nt = 0; nt < 8; nt++) {
            mx0 = fmaxf(mx0, fmaxf(s[nt][0], s[nt][1]));
            mx1 = fmaxf(mx1, fmaxf(s[nt][2], s[nt][3]));
        }
        mx0 = fmaxf(mx0, __shfl_xor_sync(0xffffffffu, mx0, 1));
        mx0 = fmaxf(mx0, __shfl_xor_sync(0xffffffffu, mx0, 2));
        mx1 = fmaxf(mx1, __shfl_xor_sync(0xffffffffu, mx1, 1));
        mx1 = fmaxf(mx1, __shfl_xor_sync(0xffffffffu, mx1, 2));
        const float nm0 = fmaxf(mrow[0], mx0);
        const float nm1 = fmaxf(mrow[1], mx1);
        const float cr0 = __expf(mrow[0] - nm0);
        const float cr1 = __expf(mrow[1] - nm1);

        float ps0 = 0.f, ps1 = 0.f;
        #pragma unroll
        for (int nt = 0; nt < 8; nt++) {
            const float p0 = (s[nt][0] > -1e29f) ? f2tf32(__expf(s[nt][0] - nm0)) : 0.f;
            const float p1 = (s[nt][1] > -1e29f) ? f2tf32(__expf(s[nt][1] - nm0)) : 0.f;
            const float p2 = (s[nt][2] > -1e29f) ? f2tf32(__expf(s[nt][2] - nm1)) : 0.f;
            const float p3 = (s[nt][3] > -1e29f) ? f2tf32(__expf(s[nt][3] - nm1)) : 0.f;
            ps0 += p0 + p1;
            ps1 += p2 + p3;
            const int cl = nt * 8 + 2 * t4;
            *(float2*)&Ssm[(m0 + g) * SS_STR + cl]     = make_float2(p0, p1);
            *(float2*)&Ssm[(m0 + g + 8) * SS_STR + cl] = make_float2(p2, p3);
        }
        ps0 += __shfl_xor_sync(0xffffffffu, ps0, 1);
        ps0 += __shfl_xor_sync(0xffffffffu, ps0, 2);
        ps1 += __shfl_xor_sync(0xffffffffu, ps1, 1);
        ps1 += __shfl_xor_sync(0xffffffffu, ps1, 2);
        lrow[0] = lrow[0] * cr0 + ps0;
        lrow[1] = lrow[1] * cr1 + ps1;
        mrow[0] = nm0;
        mrow[1] = nm1;
        __syncwarp();

        #pragma unroll
        for (int nt = 0; nt < 4; nt++) {
            acc_o[nt][0] *= cr0; acc_o[nt][1] *= cr0;
            acc_o[nt][2] *= cr1; acc_o[nt][3] *= cr1;
        }
        #pragma unroll
        for (int kk = 0; kk < 8; kk++) {
            const int kb = kk * 8;
            unsigned a0 = __float_as_uint(Ssm[(m0 + g) * SS_STR + kb + t4]);
            unsigned a1 = __float_as_uint(Ssm[(m0 + g + 8) * SS_STR + kb + t4]);
            unsigned a2 = __float_as_uint(Ssm[(m0 + g) * SS_STR + kb + t4 + 4]);
            unsigned a3 = __float_as_uint(Ssm[(m0 + g + 8) * SS_STR + kb + t4 + 4]);
            #pragma unroll
            for (int nt = 0; nt < 4; nt++) {
                const float* Vpp = &Vsm[(kb + t4) * VS_STR + nt * 8 + g];
                unsigned b0 = __float_as_uint(Vpp[0]);
                unsigned b1 = __float_as_uint(Vpp[4 * VS_STR]);
                mma_tf32(acc_o[nt][0], acc_o[nt][1], acc_o[nt][2], acc_o[nt][3],
                         a0, a1, a2, a3, b0, b1);
            }
        }
    }

    const float i0 = (lrow[0] > 0.f) ? 1.f / lrow[0] : 0.f;
    const float i1 = (lrow[1] > 0.f) ? 1.f / lrow[1] : 0.f;
    const int row = q0 + m0 + g;
    #pragma unroll
    for (int nt = 0; nt < 4; nt++) {
        const int c = nt * 8 + 2 * t4;
        *(float2*)&O[base + (size_t)row * D_ + c] =
            make_float2(acc_o[nt][0] * i0, acc_o[nt][1] * i0);
        *(float2*)&O[base + (size_t)(row + 8) * D_ + c] =
            make_float2(acc_o[nt][2] * i1, acc_o[nt][3] * i1);
    }
}

// ---------------------------------------------------------------------------
// Fused residual add + LayerNorm: warp-per-row (256 floats, 8 per lane).
// ---------------------------------------------------------------------------
__global__ __launch_bounds__(256) void add_ln_kernel(
    const float* __restrict__ X, const float* __restrict__ R,
    const float* __restrict__ gam, const float* __restrict__ bet,
    float* __restrict__ O)
{
    const int warp = threadIdx.x >> 5;
    const int lane = threadIdx.x & 31;
    const int row  = blockIdx.x * 8 + warp;
    const size_t off = (size_t)row * D_ + lane * 8;

    float4 x0 = *(const float4*)&X[off];
    float4 x1 = *(const float4*)&X[off + 4];
    float4 r0 = *(const float4*)&R[off];
    float4 r1 = *(const float4*)&R[off + 4];
    float v[8] = { x0.x + r0.x, x0.y + r0.y, x0.z + r0.z, x0.w + r0.w,
                   x1.x + r1.x, x1.y + r1.y, x1.z + r1.z, x1.w + r1.w };

    float s = 0.f;
    #pragma unroll
    for (int i = 0; i < 8; i++) s += v[i];
    #pragma unroll
    for (int o = 16; o > 0; o >>= 1) s += __shfl_xor_sync(0xffffffffu, s, o);
    const float mu = s * (1.f / 256.f);

    float s2 = 0.f;
    #pragma unroll
    for (int i = 0; i < 8; i++) { v[i] -= mu; s2 += v[i] * v[i]; }
    #pragma unroll
    for (int o = 16; o > 0; o >>= 1) s2 += __shfl_xor_sync(0xffffffffu, s2, o);
    const float rs = rsqrtf(s2 * (1.f / 256.f) + 1e-5f);

    const int c = lane * 8;
    float4 ga = *(const float4*)&gam[c];
    float4 gb = *(const float4*)&gam[c + 4];
    float4 ba = *(const float4*)&bet[c];
    float4 bb = *(const float4*)&bet[c + 4];

    float4 oa = make_float4(v[0] * rs * ga.x + ba.x, v[1] * rs * ga.y + ba.y,
                            v[2] * rs * ga.z + ba.z, v[3] * rs * ga.w + ba.w);
    float4 ob = make_float4(v[4] * rs * gb.x + bb.x, v[5] * rs * gb.y + bb.y,
                            v[6] * rs * gb.z + bb.z, v[7] * rs * gb.w + bb.w);
    *(float4*)&O[off]     = oa;
    *(float4*)&O[off + 4] = ob;
}

// ---------------------------------------------------------------------------
// Host-side orchestration
// ---------------------------------------------------------------------------
struct Scratch { float *y, *x, *kp, *vp, *att, *o, *x1, *f, *h; };

static void launch_layer(const float* Qin, const float* Vin, float* Out,
                         int li, int strict, int apply_pos,
                         void* const* d_in, const Scratch& P)
{
    const float* Wk  = (const float*)d_in[2]  + (size_t)li * D_ * D_;
    const float* bk  = (const float*)d_in[3]  + (size_t)li * D_;
    const float* Wv  = (const float*)d_in[4]  + (size_t)li * D_ * D_;
    const float* bv  = (const float*)d_in[5]  + (size_t)li * D_;
    const float* Wo  = (const float*)d_in[6]  + (size_t)li * D_ * D_;
    const float* bo  = (const float*)d_in[7]  + (size_t)li * D_;
    const float* g1  = (const float*)d_in[8]  + (size_t)li * D_;
    const float* be1 = (const float*)d_in[9]  + (size_t)li * D_;
    const float* W1  = (const float*)d_in[10] + (size_t)li * D_ * DFF_;
    const float* bf1 = (const float*)d_in[11] + (size_t)li * DFF_;
    const float* W2  = (const float*)d_in[12] + (size_t)li * DFF_ * D_;
    const float* bf2 = (const float*)d_in[13] + (size_t)li * D_;
    const float* g2  = (const float*)d_in[14] + (size_t)li * D_;
    const float* be2 = (const float*)d_in[15] + (size_t)li * D_;

    // merged K-proj (set0) + V-proj (set1) via blockIdx.z
    gemm_tc<<<dim3(D_ / 128, BS_ / 128, 2), 256>>>(
        Qin, Wk, bk, P.kp, Vin, Wv, bv, P.vp, BS_, D_, D_, 0);
    attn_tc<<<dim3(S_ / 128, B_ * H_), 256, ATTN_SMEM_BYTES>>>(P.kp, P.vp, P.att, strict);
    gemm_tc<<<dim3(D_ / 128, BS_ / 128, 1), 256>>>(
        P.att, Wo, bo, P.o, P.att, Wo, bo, P.o, BS_, D_, D_, 0);

    float* ln1out = apply_pos ? P.x1 : Out;
    add_ln_kernel<<<BS_ / 8, 256>>>(Qin, P.o, g1, be1, ln1out);

    if (apply_pos) {
        gemm_tc<<<dim3(DFF_ / 128, BS_ / 128, 1), 256>>>(
            P.x1, W1, bf1, P.h, P.x1, W1, bf1, P.h, BS_, DFF_, D_, 1);
        gemm_tc<<<dim3(D_ / 128, BS_ / 128, 1), 256>>>(
            P.h, W2, bf2, P.f, P.h, W2, bf2, P.f, BS_, D_, DFF_, 0);
        add_ln_kernel<<<BS_ / 8, 256>>>(P.x1, P.f, g2, be2, Out);
    }
}

extern "C" void kernel_launch(void* const* d_in, const int* in_sizes, int n_in,
                              void* d_out, int out_size)
{
    (void)in_sizes; (void)n_in; (void)out_size;
    const float* qe = (const float*)d_in[0];   // q_embed_data  -> x stream
    const float* qa = (const float*)d_in[1];   // qa_embed_data -> y stream

    static bool attr_done = false;
    if (!attr_done) {
        cudaFuncSetAttribute(attn_tc, cudaFuncAttributeMaxDynamicSharedMemorySize,
                             ATTN_SMEM_BYTES);
        attr_done = true;
    }

    Scratch P;
    cudaGetSymbolAddress((void**)&P.y,  g_y);
    cudaGetSymbolAddress((void**)&P.x,  g_x);
    cudaGetSymbolAddress((void**)&P.kp, g_kp);
    cudaGetSymbolAddress((void**)&P.vp, g_vp);
    cudaGetSymbolAddress((void**)&P.att, g_att);
    cudaGetSymbolAddress((void**)&P.o,  g_o);
    cudaGetSymbolAddress((void**)&P.x1, g_x1);
    cudaGetSymbolAddress((void**)&P.f,  g_f);
    cudaGetSymbolAddress((void**)&P.h,  g_h);

    // Encoder blocks (y = qa stream), mask incl. diagonal, with FFN
    launch_layer(qa,  qa,  P.y, 0, /*strict=*/0, /*apply_pos=*/1, d_in, P);
    launch_layer(P.y, P.y, P.y, 1, 0, 1, d_in, P);

    // Decoder blocks on x stream
    launch_layer(qe,  qe,  P.x, 2, /*strict=*/0, /*apply_pos=*/0, d_in, P);   // self, no FFN
    launch_layer(P.x, P.y, P.x, 3, /*strict=*/1, /*apply_pos=*/1, d_in, P);   // cross (V=y)
    launch_layer(P.x, P.x, P.x, 4, 0, 0, d_in, P);                            // self, no FFN
    launch_layer(P.x, P.y, (float*)d_out, 5, 1, 1, d_in, P);                  // cross -> out
}

// round 6
// speedup vs baseline: 1.6144x; 1.6144x over previous
#include <cuda_runtime.h>
#include <math.h>

// Problem dims (fixed by the reference)
constexpr int B_   = 64;
constexpr int S_   = 512;
constexpr int D_   = 256;
constexpr int H_   = 8;
constexpr int DK_  = 32;
constexpr int DFF_ = 1024;
constexpr int BS_  = B_ * S_;          // 32768 rows
constexpr float SCALE_ = 0.17677669529663687f; // 1/sqrt(32)

// ---------------------------------------------------------------------------
// Scratch (no allocations allowed -> __device__ globals)
// ---------------------------------------------------------------------------
__device__ float g_y  [BS_ * D_];
__device__ float g_x  [BS_ * D_];
__device__ float g_kp [BS_ * D_];
__device__ float g_vp [BS_ * D_];
__device__ float g_att[BS_ * D_];
__device__ float g_o  [BS_ * D_];
__device__ float g_x1 [BS_ * D_];
__device__ float g_f  [BS_ * D_];
__device__ float g_h  [BS_ * DFF_];

// ---------------------------------------------------------------------------
// tf32 helpers
// ---------------------------------------------------------------------------
__device__ __forceinline__ float f2tf32(float x) {
    unsigned r;
    asm("cvt.rna.tf32.f32 %0, %1;" : "=r"(r) : "f"(x));
    return __uint_as_float(r);
}

__device__ __forceinline__ void mma_tf32(
    float& c0, float& c1, float& c2, float& c3,
    unsigned a0, unsigned a1, unsigned a2, unsigned a3,
    unsigned b0, unsigned b1)
{
    asm volatile(
        "mma.sync.aligned.m16n8k8.row.col.f32.tf32.tf32.f32 "
        "{%0,%1,%2,%3}, {%4,%5,%6,%7}, {%8,%9}, {%0,%1,%2,%3};\n"
        : "+f"(c0), "+f"(c1), "+f"(c2), "+f"(c3)
        : "r"(a0), "r"(a1), "r"(a2), "r"(a3), "r"(b0), "r"(b1));
}

// ---------------------------------------------------------------------------
// Tensor-core GEMM (tf32), double-buffered (R4-proven memory patterns).
// Block 128x128, BK=16, 256 threads = 8 warps, warp tile 64x32.
// blockIdx.z selects operand set (merges K-proj / V-proj into one launch).
// ---------------------------------------------------------------------------
constexpr int APAD = 20;    // 16 + 4
constexpr int BPAD = 136;   // 128 + 8
constexpr int ASZ  = 128 * APAD;
constexpr int BSZ  = 16 * BPAD;

__global__ __launch_bounds__(256, 2) void gemm_tc(
    const float* __restrict__ A0, const float* __restrict__ W0,
    const float* __restrict__ bias0, float* __restrict__ C0,
    const float* __restrict__ A1, const float* __restrict__ W1p,
    const float* __restrict__ bias1, float* __restrict__ C1,
    int M, int N, int K, int relu)
{
    __shared__ float As[2 * ASZ];
    __shared__ float Bs[2 * BSZ];

    const float* A    = blockIdx.z ? A1    : A0;
    const float* W    = blockIdx.z ? W1p   : W0;
    const float* bias = blockIdx.z ? bias1 : bias0;
    float*       C    = blockIdx.z ? C1    : C0;

    const int tid  = threadIdx.x;
    const int lane = tid & 31;
    const int warp = tid >> 5;
    const int wm   = warp >> 2;
    const int wn   = warp & 3;
    const int g    = lane >> 2;
    const int t4   = lane & 3;
    const int mrow = wm * 64;
    const int nb   = wn * 32;

    const int bm = blockIdx.y * 128;
    const int bn = blockIdx.x * 128;
    const int nk = K >> 4;

    float acc[4][4][4];
    #pragma unroll
    for (int mt = 0; mt < 4; mt++)
        #pragma unroll
        for (int nt = 0; nt < 4; nt++)
            #pragma unroll
            for (int i = 0; i < 4; i++) acc[mt][nt][i] = 0.f;

    // stage K-tile 0 into buffer 0
    {
        #pragma unroll
        for (int i = 0; i < 2; i++) {
            const int f  = tid + (i << 8);
            const int m  = f >> 2;
            const int kq = (f & 3) << 2;
            const float4 v = *(const float4*)&A[(size_t)(bm + m) * K + kq];
            float4 w;
            w.x = f2tf32(v.x); w.y = f2tf32(v.y);
            w.z = f2tf32(v.z); w.w = f2tf32(v.w);
            *(float4*)&As[m * APAD + kq] = w;
            const int kk = f >> 5;
            const int n  = (f & 31) << 2;
            const float4 u = *(const float4*)&W[(size_t)kk * N + bn + n];
            float4 x;
            x.x = f2tf32(u.x); x.y = f2tf32(u.y);
            x.z = f2tf32(u.z); x.w = f2tf32(u.w);
            *(float4*)&Bs[kk * BPAD + n] = x;
        }
    }
    __syncthreads();

    for (int kt = 0; kt < nk; kt++) {
        const int cur = kt & 1;
        const bool pf = (kt + 1 < nk);
        float4 av[2], bv[2];
        if (pf) {
            const int k0n = (kt + 1) << 4;
            #pragma unroll
            for (int i = 0; i < 2; i++) {
                const int f = tid + (i << 8);
                av[i] = *(const float4*)&A[(size_t)(bm + (f >> 2)) * K + k0n + ((f & 3) << 2)];
                bv[i] = *(const float4*)&W[(size_t)(k0n + (f >> 5)) * N + bn + ((f & 31) << 2)];
            }
        }

        const float* Asc = As + cur * ASZ;
        const float* Bsc = Bs + cur * BSZ;
        #pragma unroll
        for (int ks = 0; ks < 16; ks += 8) {
            unsigned a[4][4], b[4][2];
            #pragma unroll
            for (int mt = 0; mt < 4; mt++) {
                const float* Ap = &Asc[(mrow + mt * 16 + g) * APAD + ks + t4];
                a[mt][0] = __float_as_uint(Ap[0]);
                a[mt][1] = __float_as_uint(Ap[8 * APAD]);
                a[mt][2] = __float_as_uint(Ap[4]);
                a[mt][3] = __float_as_uint(Ap[8 * APAD + 4]);
            }
            #pragma unroll
            for (int nt = 0; nt < 4; nt++) {
                const float* Bp = &Bsc[(ks + t4) * BPAD + nb + nt * 8 + g];
                b[nt][0] = __float_as_uint(Bp[0]);
                b[nt][1] = __float_as_uint(Bp[4 * BPAD]);
            }
            #pragma unroll
            for (int mt = 0; mt < 4; mt++)
                #pragma unroll
                for (int nt = 0; nt < 4; nt++)
                    mma_tf32(acc[mt][nt][0], acc[mt][nt][1],
                             acc[mt][nt][2], acc[mt][nt][3],
                             a[mt][0], a[mt][1], a[mt][2], a[mt][3],
                             b[nt][0], b[nt][1]);
        }

        if (pf) {
            float* Asn = As + (cur ^ 1) * ASZ;
            float* Bsn = Bs + (cur ^ 1) * BSZ;
            #pragma unroll
            for (int i = 0; i < 2; i++) {
                const int f  = tid + (i << 8);
                const int m  = f >> 2;
                const int kq = (f & 3) << 2;
                float4 w;
                w.x = f2tf32(av[i].x); w.y = f2tf32(av[i].y);
                w.z = f2tf32(av[i].z); w.w = f2tf32(av[i].w);
                *(float4*)&Asn[m * APAD + kq] = w;
                const int kk = f >> 5;
                const int n  = (f & 31) << 2;
                float4 x;
                x.x = f2tf32(bv[i].x); x.y = f2tf32(bv[i].y);
                x.z = f2tf32(bv[i].z); x.w = f2tf32(bv[i].w);
                *(float4*)&Bsn[kk * BPAD + n] = x;
            }
        }
        __syncthreads();
    }

    // epilogue: bias (+ReLU)
    #pragma unroll
    for (int mt = 0; mt < 4; mt++) {
        const int r = bm + mrow + mt * 16 + g;
        #pragma unroll
        for (int nt = 0; nt < 4; nt++) {
            const int c = bn + nb + nt * 8 + 2 * t4;
            const float b0 = bias[c], b1 = bias[c + 1];
            float v0 = acc[mt][nt][0] + b0;
            float v1 = acc[mt][nt][1] + b1;
            float v2 = acc[mt][nt][2] + b0;
            float v3 = acc[mt][nt][3] + b1;
            if (relu) {
                v0 = fmaxf(v0, 0.f); v1 = fmaxf(v1, 0.f);
                v2 = fmaxf(v2, 0.f); v3 = fmaxf(v3, 0.f);
            }
            *(float2*)&C[(size_t)r * N + c]       = make_float2(v0, v1);
            *(float2*)&C[(size_t)(r + 8) * N + c] = make_float2(v2, v3);
        }
    }
}

// ---------------------------------------------------------------------------
// Tensor-core flash attention: q-tile 128, warp owns 16 rows x ALL 64 kv.
// Softmax in registers (quad shuffles); P relayout via warp-private smem rows.
// Q is pre-scaled by 1/sqrt(dk) at staging.
// ---------------------------------------------------------------------------
constexpr int SS_STR = 68;
constexpr int KS_STR = 36;
constexpr int VS_STR = 40;
constexpr int SS_OFF = 0;
constexpr int KS_OFF = 128 * SS_STR;
constexpr int VS_OFF = KS_OFF + 64 * KS_STR;
constexpr int ATTN_SMEM_BYTES = (VS_OFF + 64 * VS_STR) * 4;  // 54272

__global__ __launch_bounds__(256) void attn_tc(
    const float* __restrict__ QK, const float* __restrict__ Vp,
    float* __restrict__ O, int strict)
{
    extern __shared__ float sm[];
    float* Ssm = sm + SS_OFF;
    float* Ksm = sm + KS_OFF;
    float* Vsm = sm + VS_OFF;

    const int qt = blockIdx.x;
    const int bh = blockIdx.y;
    const int b  = bh >> 3;
    const int h  = bh & 7;
    const int q0 = qt << 7;
    const int t    = threadIdx.x;
    const int lane = t & 31;
    const int warp = t >> 5;
    const int m0   = warp << 4;
    const int g    = lane >> 2;
    const int t4   = lane & 3;

    const size_t base = (size_t)(b * S_) * D_ + h * DK_;

    for (int i = t; i < 1024; i += 256) {
        const int r = i >> 3, c = (i & 7) << 2;
        float4 v = *(const float4*)&QK[base + (size_t)(q0 + r) * D_ + c];
        Ssm[r * SS_STR + c + 0] = f2tf32(v.x * SCALE_);
        Ssm[r * SS_STR + c + 1] = f2tf32(v.y * SCALE_);
        Ssm[r * SS_STR + c + 2] = f2tf32(v.z * SCALE_);
        Ssm[r * SS_STR + c + 3] = f2tf32(v.w * SCALE_);
    }
    __syncthreads();
    unsigned qf[4][4];
    #pragma unroll
    for (int ks = 0; ks < 4; ks++) {
        const int k = ks * 8;
        qf[ks][0] = __float_as_uint(Ssm[(m0 + g) * SS_STR + k + t4]);
        qf[ks][1] = __float_as_uint(Ssm[(m0 + g + 8) * SS_STR + k + t4]);
        qf[ks][2] = __float_as_uint(Ssm[(m0 + g) * SS_STR + k + t4 + 4]);
        qf[ks][3] = __float_as_uint(Ssm[(m0 + g + 8) * SS_STR + k + t4 + 4]);
    }

    float acc_o[4][4];
    #pragma unroll
    for (int nt = 0; nt < 4; nt++)
        #pragma unroll
        for (int i = 0; i < 4; i++) acc_o[nt][i] = 0.f;
    float mrow[2] = { -1e30f, -1e30f };
    float lrow[2] = { 0.f, 0.f };

    const int rg  = q0 + m0 + g - strict;
    const int rg8 = rg + 8;
    const int ktmax = 2 * qt + 1;

    for (int kt = 0; kt <= ktmax; kt++) {
        const int k0 = kt << 6;
        __syncthreads();
        for (int i = t; i < 512; i += 256) {
            const int rr = i >> 3, c = (i & 7) << 2;
            float4 kv = *(const float4*)&QK[base + (size_t)(k0 + rr) * D_ + c];
            Ksm[rr * KS_STR + c + 0] = f2tf32(kv.x);
            Ksm[rr * KS_STR + c + 1] = f2tf32(kv.y);
            Ksm[rr * KS_STR + c + 2] = f2tf32(kv.z);
            Ksm[rr * KS_STR + c + 3] = f2tf32(kv.w);
            float4 vv = *(const float4*)&Vp[base + (size_t)(k0 + rr) * D_ + c];
            Vsm[rr * VS_STR + c + 0] = f2tf32(vv.x);
            Vsm[rr * VS_STR + c + 1] = f2tf32(vv.y);
            Vsm[rr * VS_STR + c + 2] = f2tf32(vv.z);
            Vsm[rr * VS_STR + c + 3] = f2tf32(vv.w);
        }
        __syncthreads();

        float s[8][4];
        #pragma unroll
        for (int nt = 0; nt < 8; nt++)
            #pragma unroll
            for (int i = 0; i < 4; i++) s[nt][i] = 0.f;
        #pragma unroll
        for (int ks = 0; ks < 4; ks++) {
            const int kb = ks * 8;
            #pragma unroll
            for (int nt = 0; nt < 8; nt++) {
                const float* Kp = &Ksm[(nt * 8 + g) * KS_STR + kb + t4];
                unsigned b0 = __float_as_uint(Kp[0]);
                unsigned b1 = __float_as_uint(Kp[4]);
                mma_tf32(s[nt][0], s[nt][1], s[nt][2], s[nt][3],
                         qf[ks][0], qf[ks][1], qf[ks][2], qf[ks][3], b0, b1);
            }
        }

        #pragma unroll
        for (int nt = 0; nt < 8; nt++) {
            const int c0c = k0 + nt * 8 + 2 * t4;
            const int c1c = c0c + 1;
            s[nt][0] = (c0c <= rg ) ? s[nt][0] : -1e30f;
            s[nt][1] = (c1c <= rg ) ? s[nt][1] : -1e30f;
            s[nt][2] = (c0c <= rg8) ? s[nt][2] : -1e30f;
            s[nt][3] = (c1c <= rg8) ? s[nt][3] : -1e30f;
        }

        float mx0 = -1e30f, mx1 = -1e30f;
        #pragma unroll
        for (int nt = 0; nt < 8; nt++) {
            mx0 = fmaxf(mx0, fmaxf(s[nt][0], s[nt][1]));
            mx1 = fmaxf(mx1, fmaxf(s[nt][2], s[nt][3]));
        }
        mx0 = fmaxf(mx0, __shfl_xor_sync(0xffffffffu, mx0, 1));
        mx0 = fmaxf(mx0, __shfl_xor_sync(0xffffffffu, mx0, 2));
        mx1 = fmaxf(mx1, __shfl_xor_sync(0xffffffffu, mx1, 1));
        mx1 = fmaxf(mx1, __shfl_xor_sync(0xffffffffu, mx1, 2));
        const float nm0 = fmaxf(mrow[0], mx0);
        const float nm1 = fmaxf(mrow[1], mx1);
        const float cr0 = __expf(mrow[0] - nm0);
        const float cr1 = __expf(mrow[1] - nm1);

        float ps0 = 0.f, ps1 = 0.f;
        #pragma unroll
        for (int nt = 0; nt < 8; nt++) {
            const float p0 = (s[nt][0] > -1e29f) ? f2tf32(__expf(s[nt][0] - nm0)) : 0.f;
            const float p1 = (s[nt][1] > -1e29f) ? f2tf32(__expf(s[nt][1] - nm0)) : 0.f;
            const float p2 = (s[nt][2] > -1e29f) ? f2tf32(__expf(s[nt][2] - nm1)) : 0.f;
            const float p3 = (s[nt][3] > -1e29f) ? f2tf32(__expf(s[nt][3] - nm1)) : 0.f;
            ps0 += p0 + p1;
            ps1 += p2 + p3;
            const int cl = nt * 8 + 2 * t4;
            *(float2*)&Ssm[(m0 + g) * SS_STR + cl]     = make_float2(p0, p1);
            *(float2*)&Ssm[(m0 + g + 8) * SS_STR + cl] = make_float2(p2, p3);
        }
        ps0 += __shfl_xor_sync(0xffffffffu, ps0, 1);
        ps0 += __shfl_xor_sync(0xffffffffu, ps0, 2);
        ps1 += __shfl_xor_sync(0xffffffffu, ps1, 1);
        ps1 += __shfl_xor_sync(0xffffffffu, ps1, 2);
        lrow[0] = lrow[0] * cr0 + ps0;
        lrow[1] = lrow[1] * cr1 + ps1;
        mrow[0] = nm0;
        mrow[1] = nm1;
        __syncwarp();

        #pragma unroll
        for (int nt = 0; nt < 4; nt++) {
            acc_o[nt][0] *= cr0; acc_o[nt][1] *= cr0;
            acc_o[nt][2] *= cr1; acc_o[nt][3] *= cr1;
        }
        #pragma unroll
        for (int kk = 0; kk < 8; kk++) {
            const int kb = kk * 8;
            unsigned a0 = __float_as_uint(Ssm[(m0 + g) * SS_STR + kb + t4]);
            unsigned a1 = __float_as_uint(Ssm[(m0 + g + 8) * SS_STR + kb + t4]);
            unsigned a2 = __float_as_uint(Ssm[(m0 + g) * SS_STR + kb + t4 + 4]);
            unsigned a3 = __float_as_uint(Ssm[(m0 + g + 8) * SS_STR + kb + t4 + 4]);
            #pragma unroll
            for (int nt = 0; nt < 4; nt++) {
                const float* Vpp = &Vsm[(kb + t4) * VS_STR + nt * 8 + g];
                unsigned b0 = __float_as_uint(Vpp[0]);
                unsigned b1 = __float_as_uint(Vpp[4 * VS_STR]);
                mma_tf32(acc_o[nt][0], acc_o[nt][1], acc_o[nt][2], acc_o[nt][3],
                         a0, a1, a2, a3, b0, b1);
            }
        }
    }

    const float i0 = (lrow[0] > 0.f) ? 1.f / lrow[0] : 0.f;
    const float i1 = (lrow[1] > 0.f) ? 1.f / lrow[1] : 0.f;
    const int row = q0 + m0 + g;
    #pragma unroll
    for (int nt = 0; nt < 4; nt++) {
        const int c = nt * 8 + 2 * t4;
        *(float2*)&O[base + (size_t)row * D_ + c] =
            make_float2(acc_o[nt][0] * i0, acc_o[nt][1] * i0);
        *(float2*)&O[base + (size_t)(row + 8) * D_ + c] =
            make_float2(acc_o[nt][2] * i1, acc_o[nt][3] * i1);
    }
}

// ---------------------------------------------------------------------------
// Fused residual add + LayerNorm: warp-per-row (256 floats, 8 per lane).
// ---------------------------------------------------------------------------
__global__ __launch_bounds__(256) void add_ln_kernel(
    const float* __restrict__ X, const float* __restrict__ R,
    const float* __restrict__ gam, const float* __restrict__ bet,
    float* __restrict__ O)
{
    const int warp = threadIdx.x >> 5;
    const int lane = threadIdx.x & 31;
    const int row  = blockIdx.x * 8 + warp;
    const size_t off = (size_t)row * D_ + lane * 8;

    float4 x0 = *(const float4*)&X[off];
    float4 x1 = *(const float4*)&X[off + 4];
    float4 r0 = *(const float4*)&R[off];
    float4 r1 = *(const float4*)&R[off + 4];
    float v[8] = { x0.x + r0.x, x0.y + r0.y, x0.z + r0.z, x0.w + r0.w,
                   x1.x + r1.x, x1.y + r1.y, x1.z + r1.z, x1.w + r1.w };

    float s = 0.f;
    #pragma unroll
    for (int i = 0; i < 8; i++) s += v[i];
    #pragma unroll
    for (int o = 16; o > 0; o >>= 1) s += __shfl_xor_sync(0xffffffffu, s, o);
    const float mu = s * (1.f / 256.f);

    float s2 = 0.f;
    #pragma unroll
    for (int i = 0; i < 8; i++) { v[i] -= mu; s2 += v[i] * v[i]; }
    #pragma unroll
    for (int o = 16; o > 0; o >>= 1) s2 += __shfl_xor_sync(0xffffffffu, s2, o);
    const float rs = rsqrtf(s2 * (1.f / 256.f) + 1e-5f);

    const int c = lane * 8;
    float4 ga = *(const float4*)&gam[c];
    float4 gb = *(const float4*)&gam[c + 4];
    float4 ba = *(const float4*)&bet[c];
    float4 bb = *(const float4*)&bet[c + 4];

    float4 oa = make_float4(v[0] * rs * ga.x + ba.x, v[1] * rs * ga.y + ba.y,
                            v[2] * rs * ga.z + ba.z, v[3] * rs * ga.w + ba.w);
    float4 ob = make_float4(v[4] * rs * gb.x + bb.x, v[5] * rs * gb.y + bb.y,
                            v[6] * rs * gb.z + bb.z, v[7] * rs * gb.w + bb.w);
    *(float4*)&O[off]     = oa;
    *(float4*)&O[off + 4] = ob;
}

// ---------------------------------------------------------------------------
// Host-side orchestration
// ---------------------------------------------------------------------------
struct Scratch { float *y, *x, *kp, *vp, *att, *o, *x1, *f, *h; };

static void launch_layer(const float* Qin, const float* Vin, float* Out,
                         int li, int strict, int apply_pos,
                         void* const* d_in, const Scratch& P)
{
    const float* Wk  = (const float*)d_in[2]  + (size_t)li * D_ * D_;
    const float* bk  = (const float*)d_in[3]  + (size_t)li * D_;
    const float* Wv  = (const float*)d_in[4]  + (size_t)li * D_ * D_;
    const float* bv  = (const float*)d_in[5]  + (size_t)li * D_;
    const float* Wo  = (const float*)d_in[6]  + (size_t)li * D_ * D_;
    const float* bo  = (const float*)d_in[7]  + (size_t)li * D_;
    const float* g1  = (const float*)d_in[8]  + (size_t)li * D_;
    const float* be1 = (const float*)d_in[9]  + (size_t)li * D_;
    const float* W1  = (const float*)d_in[10] + (size_t)li * D_ * DFF_;
    const float* bf1 = (const float*)d_in[11] + (size_t)li * DFF_;
    const float* W2  = (const float*)d_in[12] + (size_t)li * DFF_ * D_;
    const float* bf2 = (const float*)d_in[13] + (size_t)li * D_;
    const float* g2  = (const float*)d_in[14] + (size_t)li * D_;
    const float* be2 = (const float*)d_in[15] + (size_t)li * D_;

    // merged K-proj (set0) + V-proj (set1) via blockIdx.z
    gemm_tc<<<dim3(D_ / 128, BS_ / 128, 2), 256>>>(
        Qin, Wk, bk, P.kp, Vin, Wv, bv, P.vp, BS_, D_, D_, 0);
    attn_tc<<<dim3(S_ / 128, B_ * H_), 256, ATTN_SMEM_BYTES>>>(P.kp, P.vp, P.att, strict);
    gemm_tc<<<dim3(D_ / 128, BS_ / 128, 1), 256>>>(
        P.att, Wo, bo, P.o, P.att, Wo, bo, P.o, BS_, D_, D_, 0);

    float* ln1out = apply_pos ? P.x1 : Out;
    add_ln_kernel<<<BS_ / 8, 256>>>(Qin, P.o, g1, be1, ln1out);

    if (apply_pos) {
        gemm_tc<<<dim3(DFF_ / 128, BS_ / 128, 1), 256>>>(
            P.x1, W1, bf1, P.h, P.x1, W1, bf1, P.h, BS_, DFF_, D_, 1);
        gemm_tc<<<dim3(D_ / 128, BS_ / 128, 1), 256>>>(
            P.h, W2, bf2, P.f, P.h, W2, bf2, P.f, BS_, D_, DFF_, 0);
        add_ln_kernel<<<BS_ / 8, 256>>>(P.x1, P.f, g2, be2, Out);
    }
}

extern "C" void kernel_launch(void* const* d_in, const int* in_sizes, int n_in,
                              void* d_out, int out_size)
{
    (void)in_sizes; (void)n_in; (void)out_size;
    const float* qe = (const float*)d_in[0];   // q_embed_data  -> x stream
    const float* qa = (const float*)d_in[1];   // qa_embed_data -> y stream

    static bool attr_done = false;
    if (!attr_done) {
        cudaFuncSetAttribute(attn_tc, cudaFuncAttributeMaxDynamicSharedMemorySize,
                             ATTN_SMEM_BYTES);
        attr_done = true;
    }

    Scratch P;
    cudaGetSymbolAddress((void**)&P.y,  g_y);
    cudaGetSymbolAddress((void**)&P.x,  g_x);
    cudaGetSymbolAddress((void**)&P.kp, g_kp);
    cudaGetSymbolAddress((void**)&P.vp, g_vp);
    cudaGetSymbolAddress((void**)&P.att, g_att);
    cudaGetSymbolAddress((void**)&P.o,  g_o);
    cudaGetSymbolAddress((void**)&P.x1, g_x1);
    cudaGetSymbolAddress((void**)&P.f,  g_f);
    cudaGetSymbolAddress((void**)&P.h,  g_h);

    // Encoder blocks (y = qa stream), mask incl. diagonal, with FFN
    launch_layer(qa,  qa,  P.y, 0, /*strict=*/0, /*apply_pos=*/1, d_in, P);
    launch_layer(P.y, P.y, P.y, 1, 0, 1, d_in, P);

    // Decoder blocks on x stream
    launch_layer(qe,  qe,  P.x, 2, /*strict=*/0, /*apply_pos=*/0, d_in, P);   // self, no FFN
    launch_layer(P.x, P.y, P.x, 3, /*strict=*/1, /*apply_pos=*/1, d_in, P);   // cross (V=y)
    launch_layer(P.x, P.x, P.x, 4, 0, 0, d_in, P);                            // self, no FFN
    launch_layer(P.x, P.y, (float*)d_out, 5, 1, 1, d_in, P);                  // cross -> out
}

// round 7
// speedup vs baseline: 1.6401x; 1.0159x over previous
#include <cuda_runtime.h>
#include <math.h>

// Problem dims (fixed by the reference)
constexpr int B_   = 64;
constexpr int S_   = 512;
constexpr int D_   = 256;
constexpr int H_   = 8;
constexpr int DK_  = 32;
constexpr int DFF_ = 1024;
constexpr int BS_  = B_ * S_;          // 32768 rows
constexpr float SCALE_ = 0.17677669529663687f; // 1/sqrt(32)

// ---------------------------------------------------------------------------
// Scratch (no allocations allowed -> __device__ globals)
// ---------------------------------------------------------------------------
__device__ float g_y  [BS_ * D_];
__device__ float g_x  [BS_ * D_];
__device__ float g_kp [BS_ * D_];
__device__ float g_vp [BS_ * D_];
__device__ float g_att[BS_ * D_];
__device__ float g_o  [BS_ * D_];
__device__ float g_x1 [BS_ * D_];
__device__ float g_f  [BS_ * D_];
__device__ float g_h  [BS_ * DFF_];

// ---------------------------------------------------------------------------
// tf32 helpers
// ---------------------------------------------------------------------------
__device__ __forceinline__ float f2tf32(float x) {
    unsigned r;
    asm("cvt.rna.tf32.f32 %0, %1;" : "=r"(r) : "f"(x));
    return __uint_as_float(r);
}

__device__ __forceinline__ void mma_tf32(
    float& c0, float& c1, float& c2, float& c3,
    unsigned a0, unsigned a1, unsigned a2, unsigned a3,
    unsigned b0, unsigned b1)
{
    asm volatile(
        "mma.sync.aligned.m16n8k8.row.col.f32.tf32.tf32.f32 "
        "{%0,%1,%2,%3}, {%4,%5,%6,%7}, {%8,%9}, {%0,%1,%2,%3};\n"
        : "+f"(c0), "+f"(c1), "+f"(c2), "+f"(c3)
        : "r"(a0), "r"(a1), "r"(a2), "r"(a3), "r"(b0), "r"(b1));
}

// ---------------------------------------------------------------------------
// Tensor-core GEMM (tf32), double-buffered, FAT TILES: block 128x256, BK=16,
// 256 threads = 8 warps (2x4), warp tile 64x64 (acc = 128 regs/thread).
// Cuts per-SM smem LDS traffic per MAC by 1/3 vs 128x128 (BW-bound fix).
// N must be divisible by 256 (true: 256, 1024). Dynamic smem 54272 B.
// blockIdx.z selects operand set (merges K-proj / V-proj into one launch).
// ---------------------------------------------------------------------------
constexpr int APAD  = 20;     // 16 + 4
constexpr int BPAD2 = 264;    // 256 + 8  (264 mod 32 == 8 -> conflict-free frags)
constexpr int ASZ   = 128 * APAD;       // 2560 floats
constexpr int BSZ2  = 16 * BPAD2;       // 4224 floats
constexpr int GEMM_SMEM_BYTES = (2 * ASZ + 2 * BSZ2) * 4;   // 54272

__global__ __launch_bounds__(256, 1) void gemm_tc(
    const float* __restrict__ A0, const float* __restrict__ W0,
    const float* __restrict__ bias0, float* __restrict__ C0,
    const float* __restrict__ A1, const float* __restrict__ W1p,
    const float* __restrict__ bias1, float* __restrict__ C1,
    int M, int N, int K, int relu)
{
    extern __shared__ float gsm[];
    float* As = gsm;                 // 2 stages of 128 x APAD
    float* Bs = gsm + 2 * ASZ;       // 2 stages of 16 x BPAD2

    const float* A    = blockIdx.z ? A1    : A0;
    const float* W    = blockIdx.z ? W1p   : W0;
    const float* bias = blockIdx.z ? bias1 : bias0;
    float*       C    = blockIdx.z ? C1    : C0;

    const int tid  = threadIdx.x;
    const int lane = tid & 31;
    const int warp = tid >> 5;
    const int wm   = warp >> 2;          // 0..1
    const int wn   = warp & 3;           // 0..3
    const int g    = lane >> 2;
    const int t4   = lane & 3;
    const int mrow = wm * 64;
    const int nb   = wn * 64;

    const int bm = blockIdx.y * 128;
    const int bn = blockIdx.x * 256;
    const int nk = K >> 4;

    float acc[4][8][4];
    #pragma unroll
    for (int mt = 0; mt < 4; mt++)
        #pragma unroll
        for (int nt = 0; nt < 8; nt++)
            #pragma unroll
            for (int i = 0; i < 4; i++) acc[mt][nt][i] = 0.f;

    // ---- stage K-tile 0 into buffer 0
    {
        #pragma unroll
        for (int i = 0; i < 2; i++) {       // A: 128x16 = 512 float4
            const int f  = tid + (i << 8);
            const int m  = f >> 2;
            const int kq = (f & 3) << 2;
            const float4 v = *(const float4*)&A[(size_t)(bm + m) * K + kq];
            float4 w;
            w.x = f2tf32(v.x); w.y = f2tf32(v.y);
            w.z = f2tf32(v.z); w.w = f2tf32(v.w);
            *(float4*)&As[m * APAD + kq] = w;
        }
        #pragma unroll
        for (int i = 0; i < 4; i++) {       // B: 16x256 = 1024 float4
            const int f  = tid + (i << 8);
            const int kk = f >> 6;
            const int n  = (f & 63) << 2;
            const float4 u = *(const float4*)&W[(size_t)kk * N + bn + n];
            float4 x;
            x.x = f2tf32(u.x); x.y = f2tf32(u.y);
            x.z = f2tf32(u.z); x.w = f2tf32(u.w);
            *(float4*)&Bs[kk * BPAD2 + n] = x;
        }
    }
    __syncthreads();

    for (int kt = 0; kt < nk; kt++) {
        const int cur = kt & 1;
        const bool pf = (kt + 1 < nk);
        float4 av[2], bv[4];
        if (pf) {
            const int k0n = (kt + 1) << 4;
            #pragma unroll
            for (int i = 0; i < 2; i++) {
                const int f = tid + (i << 8);
                av[i] = *(const float4*)&A[(size_t)(bm + (f >> 2)) * K + k0n + ((f & 3) << 2)];
            }
            #pragma unroll
            for (int i = 0; i < 4; i++) {
                const int f = tid + (i << 8);
                bv[i] = *(const float4*)&W[(size_t)(k0n + (f >> 6)) * N + bn + ((f & 63) << 2)];
            }
        }

        const float* Asc = As + cur * ASZ;
        const float* Bsc = Bs + cur * BSZ2;
        #pragma unroll
        for (int ks = 0; ks < 16; ks += 8) {
            unsigned a[4][4], b[8][2];
            #pragma unroll
            for (int mt = 0; mt < 4; mt++) {
                const float* Ap = &Asc[(mrow + mt * 16 + g) * APAD + ks + t4];
                a[mt][0] = __float_as_uint(Ap[0]);
                a[mt][1] = __float_as_uint(Ap[8 * APAD]);
                a[mt][2] = __float_as_uint(Ap[4]);
                a[mt][3] = __float_as_uint(Ap[8 * APAD + 4]);
            }
            #pragma unroll
            for (int nt = 0; nt < 8; nt++) {
                const float* Bp = &Bsc[(ks + t4) * BPAD2 + nb + nt * 8 + g];
                b[nt][0] = __float_as_uint(Bp[0]);
                b[nt][1] = __float_as_uint(Bp[4 * BPAD2]);
            }
            #pragma unroll
            for (int mt = 0; mt < 4; mt++)
                #pragma unroll
                for (int nt = 0; nt < 8; nt++)
                    mma_tf32(acc[mt][nt][0], acc[mt][nt][1],
                             acc[mt][nt][2], acc[mt][nt][3],
                             a[mt][0], a[mt][1], a[mt][2], a[mt][3],
                             b[nt][0], b[nt][1]);
        }

        if (pf) {
            float* Asn = As + (cur ^ 1) * ASZ;
            float* Bsn = Bs + (cur ^ 1) * BSZ2;
            #pragma unroll
            for (int i = 0; i < 2; i++) {
                const int f  = tid + (i << 8);
                const int m  = f >> 2;
                const int kq = (f & 3) << 2;
                float4 w;
                w.x = f2tf32(av[i].x); w.y = f2tf32(av[i].y);
                w.z = f2tf32(av[i].z); w.w = f2tf32(av[i].w);
                *(float4*)&Asn[m * APAD + kq] = w;
            }
            #pragma unroll
            for (int i = 0; i < 4; i++) {
                const int f  = tid + (i << 8);
                const int kk = f >> 6;
                const int n  = (f & 63) << 2;
                float4 x;
                x.x = f2tf32(bv[i].x); x.y = f2tf32(bv[i].y);
                x.z = f2tf32(bv[i].z); x.w = f2tf32(bv[i].w);
                *(float4*)&Bsn[kk * BPAD2 + n] = x;
            }
        }
        __syncthreads();
    }

    // ---- epilogue: bias (+ReLU)
    #pragma unroll
    for (int mt = 0; mt < 4; mt++) {
        const int r = bm + mrow + mt * 16 + g;
        #pragma unroll
        for (int nt = 0; nt < 8; nt++) {
            const int c = bn + nb + nt * 8 + 2 * t4;
            const float b0 = bias[c], b1 = bias[c + 1];
            float v0 = acc[mt][nt][0] + b0;
            float v1 = acc[mt][nt][1] + b1;
            float v2 = acc[mt][nt][2] + b0;
            float v3 = acc[mt][nt][3] + b1;
            if (relu) {
                v0 = fmaxf(v0, 0.f); v1 = fmaxf(v1, 0.f);
                v2 = fmaxf(v2, 0.f); v3 = fmaxf(v3, 0.f);
            }
            *(float2*)&C[(size_t)r * N + c]       = make_float2(v0, v1);
            *(float2*)&C[(size_t)(r + 8) * N + c] = make_float2(v2, v3);
        }
    }
}

// ---------------------------------------------------------------------------
// Tensor-core flash attention: q-tile 128, warp owns 16 rows x ALL 64 kv.
// Softmax in registers (quad shuffles); P relayout via warp-private smem rows.
// Q is pre-scaled by 1/sqrt(dk) at staging.
// ---------------------------------------------------------------------------
constexpr int SS_STR = 68;
constexpr int KS_STR = 36;
constexpr int VS_STR = 40;
constexpr int SS_OFF = 0;
constexpr int KS_OFF = 128 * SS_STR;
constexpr int VS_OFF = KS_OFF + 64 * KS_STR;
constexpr int ATTN_SMEM_BYTES = (VS_OFF + 64 * VS_STR) * 4;  // 54272

__global__ __launch_bounds__(256) void attn_tc(
    const float* __restrict__ QK, const float* __restrict__ Vp,
    float* __restrict__ O, int strict)
{
    extern __shared__ float sm[];
    float* Ssm = sm + SS_OFF;
    float* Ksm = sm + KS_OFF;
    float* Vsm = sm + VS_OFF;

    const int qt = blockIdx.x;
    const int bh = blockIdx.y;
    const int b  = bh >> 3;
    const int h  = bh & 7;
    const int q0 = qt << 7;
    const int t    = threadIdx.x;
    const int lane = t & 31;
    const int warp = t >> 5;
    const int m0   = warp << 4;
    const int g    = lane >> 2;
    const int t4   = lane & 3;

    const size_t base = (size_t)(b * S_) * D_ + h * DK_;

    for (int i = t; i < 1024; i += 256) {
        const int r = i >> 3, c = (i & 7) << 2;
        float4 v = *(const float4*)&QK[base + (size_t)(q0 + r) * D_ + c];
        Ssm[r * SS_STR + c + 0] = f2tf32(v.x * SCALE_);
        Ssm[r * SS_STR + c + 1] = f2tf32(v.y * SCALE_);
        Ssm[r * SS_STR + c + 2] = f2tf32(v.z * SCALE_);
        Ssm[r * SS_STR + c + 3] = f2tf32(v.w * SCALE_);
    }
    __syncthreads();
    unsigned qf[4][4];
    #pragma unroll
    for (int ks = 0; ks < 4; ks++) {
        const int k = ks * 8;
        qf[ks][0] = __float_as_uint(Ssm[(m0 + g) * SS_STR + k + t4]);
        qf[ks][1] = __float_as_uint(Ssm[(m0 + g + 8) * SS_STR + k + t4]);
        qf[ks][2] = __float_as_uint(Ssm[(m0 + g) * SS_STR + k + t4 + 4]);
        qf[ks][3] = __float_as_uint(Ssm[(m0 + g + 8) * SS_STR + k + t4 + 4]);
    }

    float acc_o[4][4];
    #pragma unroll
    for (int nt = 0; nt < 4; nt++)
        #pragma unroll
        for (int i = 0; i < 4; i++) acc_o[nt][i] = 0.f;
    float mrow[2] = { -1e30f, -1e30f };
    float lrow[2] = { 0.f, 0.f };

    const int rg  = q0 + m0 + g - strict;
    const int rg8 = rg + 8;
    const int ktmax = 2 * qt + 1;

    for (int kt = 0; kt <= ktmax; kt++) {
        const int k0 = kt << 6;
        __syncthreads();
        for (int i = t; i < 512; i += 256) {
            const int rr = i >> 3, c = (i & 7) << 2;
            float4 kv = *(const float4*)&QK[base + (size_t)(k0 + rr) * D_ + c];
            Ksm[rr * KS_STR + c + 0] = f2tf32(kv.x);
            Ksm[rr * KS_STR + c + 1] = f2tf32(kv.y);
            Ksm[rr * KS_STR + c + 2] = f2tf32(kv.z);
            Ksm[rr * KS_STR + c + 3] = f2tf32(kv.w);
            float4 vv = *(const float4*)&Vp[base + (size_t)(k0 + rr) * D_ + c];
            Vsm[rr * VS_STR + c + 0] = f2tf32(vv.x);
            Vsm[rr * VS_STR + c + 1] = f2tf32(vv.y);
            Vsm[rr * VS_STR + c + 2] = f2tf32(vv.z);
            Vsm[rr * VS_STR + c + 3] = f2tf32(vv.w);
        }
        __syncthreads();

        float s[8][4];
        #pragma unroll
        for (int nt = 0; nt < 8; nt++)
            #pragma unroll
            for (int i = 0; i < 4; i++) s[nt][i] = 0.f;
        #pragma unroll
        for (int ks = 0; ks < 4; ks++) {
            const int kb = ks * 8;
            #pragma unroll
            for (int nt = 0; nt < 8; nt++) {
                const float* Kp = &Ksm[(nt * 8 + g) * KS_STR + kb + t4];
                unsigned b0 = __float_as_uint(Kp[0]);
                unsigned b1 = __float_as_uint(Kp[4]);
                mma_tf32(s[nt][0], s[nt][1], s[nt][2], s[nt][3],
                         qf[ks][0], qf[ks][1], qf[ks][2], qf[ks][3], b0, b1);
            }
        }

        #pragma unroll
        for (int nt = 0; nt < 8; nt++) {
            const int c0c = k0 + nt * 8 + 2 * t4;
            const int c1c = c0c + 1;
            s[nt][0] = (c0c <= rg ) ? s[nt][0] : -1e30f;
            s[nt][1] = (c1c <= rg ) ? s[nt][1] : -1e30f;
            s[nt][2] = (c0c <= rg8) ? s[nt][2] : -1e30f;
            s[nt][3] = (c1c <= rg8) ? s[nt][3] : -1e30f;
        }

        float mx0 = -1e30f, mx1 = -1e30f;
        #pragma unroll
        for (int nt = 0; nt < 8; nt++) {
            mx0 = fmaxf(mx0, fmaxf(s[nt][0], s[nt][1]));
            mx1 = fmaxf(mx1, fmaxf(s[nt][2], s[nt][3]));
        }
        mx0 = fmaxf(mx0, __shfl_xor_sync(0xffffffffu, mx0, 1));
        mx0 = fmaxf(mx0, __shfl_xor_sync(0xffffffffu, mx0, 2));
        mx1 = fmaxf(mx1, __shfl_xor_sync(0xffffffffu, mx1, 1));
        mx1 = fmaxf(mx1, __shfl_xor_sync(0xffffffffu, mx1, 2));
        const float nm0 = fmaxf(mrow[0], mx0);
        const float nm1 = fmaxf(mrow[1], mx1);
        const float cr0 = __expf(mrow[0] - nm0);
        const float cr1 = __expf(mrow[1] - nm1);

        float ps0 = 0.f, ps1 = 0.f;
        #pragma unroll
        for (int nt = 0; nt < 8; nt++) {
            const float p0 = (s[nt][0] > -1e29f) ? f2tf32(__expf(s[nt][0] - nm0)) : 0.f;
            const float p1 = (s[nt][1] > -1e29f) ? f2tf32(__expf(s[nt][1] - nm0)) : 0.f;
            const float p2 = (s[nt][2] > -1e29f) ? f2tf32(__expf(s[nt][2] - nm1)) : 0.f;
            const float p3 = (s[nt][3] > -1e29f) ? f2tf32(__expf(s[nt][3] - nm1)) : 0.f;
            ps0 += p0 + p1;
            ps1 += p2 + p3;
            const int cl = nt * 8 + 2 * t4;
            *(float2*)&Ssm[(m0 + g) * SS_STR + cl]     = make_float2(p0, p1);
            *(float2*)&Ssm[(m0 + g + 8) * SS_STR + cl] = make_float2(p2, p3);
        }
        ps0 += __shfl_xor_sync(0xffffffffu, ps0, 1);
        ps0 += __shfl_xor_sync(0xffffffffu, ps0, 2);
        ps1 += __shfl_xor_sync(0xffffffffu, ps1, 1);
        ps1 += __shfl_xor_sync(0xffffffffu, ps1, 2);
        lrow[0] = lrow[0] * cr0 + ps0;
        lrow[1] = lrow[1] * cr1 + ps1;
        mrow[0] = nm0;
        mrow[1] = nm1;
        __syncwarp();

        #pragma unroll
        for (int nt = 0; nt < 4; nt++) {
            acc_o[nt][0] *= cr0; acc_o[nt][1] *= cr0;
            acc_o[nt][2] *= cr1; acc_o[nt][3] *= cr1;
        }
        #pragma unroll
        for (int kk = 0; kk < 8; kk++) {
            const int kb = kk * 8;
            unsigned a0 = __float_as_uint(Ssm[(m0 + g) * SS_STR + kb + t4]);
            unsigned a1 = __float_as_uint(Ssm[(m0 + g + 8) * SS_STR + kb + t4]);
            unsigned a2 = __float_as_uint(Ssm[(m0 + g) * SS_STR + kb + t4 + 4]);
            unsigned a3 = __float_as_uint(Ssm[(m0 + g + 8) * SS_STR + kb + t4 + 4]);
            #pragma unroll
            for (int nt = 0; nt < 4; nt++) {
                const float* Vpp = &Vsm[(kb + t4) * VS_STR + nt * 8 + g];
                unsigned b0 = __float_as_uint(Vpp[0]);
                unsigned b1 = __float_as_uint(Vpp[4 * VS_STR]);
                mma_tf32(acc_o[nt][0], acc_o[nt][1], acc_o[nt][2], acc_o[nt][3],
                         a0, a1, a2, a3, b0, b1);
            }
        }
    }

    const float i0 = (lrow[0] > 0.f) ? 1.f / lrow[0] : 0.f;
    const float i1 = (lrow[1] > 0.f) ? 1.f / lrow[1] : 0.f;
    const int row = q0 + m0 + g;
    #pragma unroll
    for (int nt = 0; nt < 4; nt++) {
        const int c = nt * 8 + 2 * t4;
        *(float2*)&O[base + (size_t)row * D_ + c] =
            make_float2(acc_o[nt][0] * i0, acc_o[nt][1] * i0);
        *(float2*)&O[base + (size_t)(row + 8) * D_ + c] =
            make_float2(acc_o[nt][2] * i1, acc_o[nt][3] * i1);
    }
}

// ---------------------------------------------------------------------------
// Fused residual add + LayerNorm: warp-per-row (256 floats, 8 per lane).
// ---------------------------------------------------------------------------
__global__ __launch_bounds__(256) void add_ln_kernel(
    const float* __restrict__ X, const float* __restrict__ R,
    const float* __restrict__ gam, const float* __restrict__ bet,
    float* __restrict__ O)
{
    const int warp = threadIdx.x >> 5;
    const int lane = threadIdx.x & 31;
    const int row  = blockIdx.x * 8 + warp;
    const size_t off = (size_t)row * D_ + lane * 8;

    float4 x0 = *(const float4*)&X[off];
    float4 x1 = *(const float4*)&X[off + 4];
    float4 r0 = *(const float4*)&R[off];
    float4 r1 = *(const float4*)&R[off + 4];
    float v[8] = { x0.x + r0.x, x0.y + r0.y, x0.z + r0.z, x0.w + r0.w,
                   x1.x + r1.x, x1.y + r1.y, x1.z + r1.z, x1.w + r1.w };

    float s = 0.f;
    #pragma unroll
    for (int i = 0; i < 8; i++) s += v[i];
    #pragma unroll
    for (int o = 16; o > 0; o >>= 1) s += __shfl_xor_sync(0xffffffffu, s, o);
    const float mu = s * (1.f / 256.f);

    float s2 = 0.f;
    #pragma unroll
    for (int i = 0; i < 8; i++) { v[i] -= mu; s2 += v[i] * v[i]; }
    #pragma unroll
    for (int o = 16; o > 0; o >>= 1) s2 += __shfl_xor_sync(0xffffffffu, s2, o);
    const float rs = rsqrtf(s2 * (1.f / 256.f) + 1e-5f);

    const int c = lane * 8;
    float4 ga = *(const float4*)&gam[c];
    float4 gb = *(const float4*)&gam[c + 4];
    float4 ba = *(const float4*)&bet[c];
    float4 bb = *(const float4*)&bet[c + 4];

    float4 oa = make_float4(v[0] * rs * ga.x + ba.x, v[1] * rs * ga.y + ba.y,
                            v[2] * rs * ga.z + ba.z, v[3] * rs * ga.w + ba.w);
    float4 ob = make_float4(v[4] * rs * gb.x + bb.x, v[5] * rs * gb.y + bb.y,
                            v[6] * rs * gb.z + bb.z, v[7] * rs * gb.w + bb.w);
    *(float4*)&O[off]     = oa;
    *(float4*)&O[off + 4] = ob;
}

// ---------------------------------------------------------------------------
// Host-side orchestration
// ---------------------------------------------------------------------------
struct Scratch { float *y, *x, *kp, *vp, *att, *o, *x1, *f, *h; };

static void launch_layer(const float* Qin, const float* Vin, float* Out,
                         int li, int strict, int apply_pos,
                         void* const* d_in, const Scratch& P)
{
    const float* Wk  = (const float*)d_in[2]  + (size_t)li * D_ * D_;
    const float* bk  = (const float*)d_in[3]  + (size_t)li * D_;
    const float* Wv  = (const float*)d_in[4]  + (size_t)li * D_ * D_;
    const float* bv  = (const float*)d_in[5]  + (size_t)li * D_;
    const float* Wo  = (const float*)d_in[6]  + (size_t)li * D_ * D_;
    const float* bo  = (const float*)d_in[7]  + (size_t)li * D_;
    const float* g1  = (const float*)d_in[8]  + (size_t)li * D_;
    const float* be1 = (const float*)d_in[9]  + (size_t)li * D_;
    const float* W1  = (const float*)d_in[10] + (size_t)li * D_ * DFF_;
    const float* bf1 = (const float*)d_in[11] + (size_t)li * DFF_;
    const float* W2  = (const float*)d_in[12] + (size_t)li * DFF_ * D_;
    const float* bf2 = (const float*)d_in[13] + (size_t)li * D_;
    const float* g2  = (const float*)d_in[14] + (size_t)li * D_;
    const float* be2 = (const float*)d_in[15] + (size_t)li * D_;

    // merged K-proj (set0) + V-proj (set1) via blockIdx.z  (N=256 -> grid.x=1)
    gemm_tc<<<dim3(D_ / 256, BS_ / 128, 2), 256, GEMM_SMEM_BYTES>>>(
        Qin, Wk, bk, P.kp, Vin, Wv, bv, P.vp, BS_, D_, D_, 0);
    attn_tc<<<dim3(S_ / 128, B_ * H_), 256, ATTN_SMEM_BYTES>>>(P.kp, P.vp, P.att, strict);
    gemm_tc<<<dim3(D_ / 256, BS_ / 128, 1), 256, GEMM_SMEM_BYTES>>>(
        P.att, Wo, bo, P.o, P.att, Wo, bo, P.o, BS_, D_, D_, 0);

    float* ln1out = apply_pos ? P.x1 : Out;
    add_ln_kernel<<<BS_ / 8, 256>>>(Qin, P.o, g1, be1, ln1out);

    if (apply_pos) {
        gemm_tc<<<dim3(DFF_ / 256, BS_ / 128, 1), 256, GEMM_SMEM_BYTES>>>(
            P.x1, W1, bf1, P.h, P.x1, W1, bf1, P.h, BS_, DFF_, D_, 1);
        gemm_tc<<<dim3(D_ / 256, BS_ / 128, 1), 256, GEMM_SMEM_BYTES>>>(
            P.h, W2, bf2, P.f, P.h, W2, bf2, P.f, BS_, D_, DFF_, 0);
        add_ln_kernel<<<BS_ / 8, 256>>>(P.x1, P.f, g2, be2, Out);
    }
}

extern "C" void kernel_launch(void* const* d_in, const int* in_sizes, int n_in,
                              void* d_out, int out_size)
{
    (void)in_sizes; (void)n_in; (void)out_size;
    const float* qe = (const float*)d_in[0];   // q_embed_data  -> x stream
    const float* qa = (const float*)d_in[1];   // qa_embed_data -> y stream

    static bool attr_done = false;
    if (!attr_done) {
        cudaFuncSetAttribute(attn_tc, cudaFuncAttributeMaxDynamicSharedMemorySize,
                             ATTN_SMEM_BYTES);
        cudaFuncSetAttribute(gemm_tc, cudaFuncAttributeMaxDynamicSharedMemorySize,
                             GEMM_SMEM_BYTES);
        attr_done = true;
    }

    Scratch P;
    cudaGetSymbolAddress((void**)&P.y,  g_y);
    cudaGetSymbolAddress((void**)&P.x,  g_x);
    cudaGetSymbolAddress((void**)&P.kp, g_kp);
    cudaGetSymbolAddress((void**)&P.vp, g_vp);
    cudaGetSymbolAddress((void**)&P.att, g_att);
    cudaGetSymbolAddress((void**)&P.o,  g_o);
    cudaGetSymbolAddress((void**)&P.x1, g_x1);
    cudaGetSymbolAddress((void**)&P.f,  g_f);
    cudaGetSymbolAddress((void**)&P.h,  g_h);

    // Encoder blocks (y = qa stream), mask incl. diagonal, with FFN
    launch_layer(qa,  qa,  P.y, 0, /*strict=*/0, /*apply_pos=*/1, d_in, P);
    launch_layer(P.y, P.y, P.y, 1, 0, 1, d_in, P);

    // Decoder blocks on x stream
    launch_layer(qe,  qe,  P.x, 2, /*strict=*/0, /*apply_pos=*/0, d_in, P);   // self, no FFN
    launch_layer(P.x, P.y, P.x, 3, /*strict=*/1, /*apply_pos=*/1, d_in, P);   // cross (V=y)
    launch_layer(P.x, P.x, P.x, 4, 0, 0, d_in, P);                            // self, no FFN
    launch_layer(P.x, P.y, (float*)d_out, 5, 1, 1, d_in, P);                  // cross -> out
}

// round 8
// speedup vs baseline: 1.8403x; 1.1221x over previous
#include <cuda_runtime.h>
#include <cuda_fp16.h>
#include <math.h>

// Problem dims (fixed by the reference)
constexpr int B_   = 64;
constexpr int S_   = 512;
constexpr int D_   = 256;
constexpr int H_   = 8;
constexpr int DK_  = 32;
constexpr int DFF_ = 1024;
constexpr int BS_  = B_ * S_;          // 32768 rows
constexpr float SCALE_ = 0.17677669529663687f; // 1/sqrt(32)

// ---------------------------------------------------------------------------
// Scratch (no allocations allowed -> __device__ globals)
// ---------------------------------------------------------------------------
__device__ float g_y  [BS_ * D_];
__device__ float g_x  [BS_ * D_];
__device__ float g_kp [BS_ * D_];
__device__ float g_vp [BS_ * D_];
__device__ float g_att[BS_ * D_];
__device__ float g_o  [BS_ * D_];
__device__ float g_x1 [BS_ * D_];
__device__ float g_f  [BS_ * D_];
__device__ float g_h  [BS_ * DFF_];

// ---------------------------------------------------------------------------
// helpers
// ---------------------------------------------------------------------------
__device__ __forceinline__ float f2tf32(float x) {
    unsigned r;
    asm("cvt.rna.tf32.f32 %0, %1;" : "=r"(r) : "f"(x));
    return __uint_as_float(r);
}

__device__ __forceinline__ unsigned pack_h2(float lo, float hi) {
    unsigned u;
    asm("cvt.rn.f16x2.f32 %0, %1, %2;" : "=r"(u) : "f"(hi), "f"(lo));
    return u;
}

__device__ __forceinline__ void mma_tf32(
    float& c0, float& c1, float& c2, float& c3,
    unsigned a0, unsigned a1, unsigned a2, unsigned a3,
    unsigned b0, unsigned b1)
{
    asm volatile(
        "mma.sync.aligned.m16n8k8.row.col.f32.tf32.tf32.f32 "
        "{%0,%1,%2,%3}, {%4,%5,%6,%7}, {%8,%9}, {%0,%1,%2,%3};\n"
        : "+f"(c0), "+f"(c1), "+f"(c2), "+f"(c3)
        : "r"(a0), "r"(a1), "r"(a2), "r"(a3), "r"(b0), "r"(b1));
}

__device__ __forceinline__ void mma_f16(
    float& c0, float& c1, float& c2, float& c3,
    unsigned a0, unsigned a1, unsigned a2, unsigned a3,
    unsigned b0, unsigned b1)
{
    asm volatile(
        "mma.sync.aligned.m16n8k16.row.col.f32.f16.f16.f32 "
        "{%0,%1,%2,%3}, {%4,%5,%6,%7}, {%8,%9}, {%0,%1,%2,%3};\n"
        : "+f"(c0), "+f"(c1), "+f"(c2), "+f"(c3)
        : "r"(a0), "r"(a1), "r"(a2), "r"(a3), "r"(b0), "r"(b1));
}

__device__ __forceinline__ void ldsm_x4(
    unsigned& r0, unsigned& r1, unsigned& r2, unsigned& r3, unsigned addr)
{
    asm volatile("ldmatrix.sync.aligned.m8n8.x4.shared.b16 {%0,%1,%2,%3}, [%4];"
                 : "=r"(r0), "=r"(r1), "=r"(r2), "=r"(r3) : "r"(addr));
}

__device__ __forceinline__ void ldsm_x4_t(
    unsigned& r0, unsigned& r1, unsigned& r2, unsigned& r3, unsigned addr)
{
    asm volatile("ldmatrix.sync.aligned.m8n8.x4.trans.shared.b16 {%0,%1,%2,%3}, [%4];"
                 : "=r"(r0), "=r"(r1), "=r"(r2), "=r"(r3) : "r"(addr));
}

// ---------------------------------------------------------------------------
// fp16 tensor-core GEMM, double-buffered, ldmatrix fragments.
// Block 128x256, BK=16, 256 threads = 8 warps (2x4), warp tile 64x64.
// A smem: half[128][40] per stage (stride 80B -> ldmatrix conflict-free)
// B smem: half[16][264] per stage (stride 528B -> ldmatrix.trans conflict-free)
// fp32 accum; inputs rounded to fp16 (same 11-bit significand as tf32).
// blockIdx.z selects operand set (merged K/V projection launch).
// ---------------------------------------------------------------------------
constexpr int ASTR = 40;                 // halves
constexpr int BSTR = 264;                // halves
constexpr int ASZH = 128 * ASTR;         // 5120 halves / stage
constexpr int BSZH = 16 * BSTR;          // 4224 halves / stage

__global__ __launch_bounds__(256, 1) void gemm_tc(
    const float* __restrict__ A0, const float* __restrict__ W0,
    const float* __restrict__ bias0, float* __restrict__ C0,
    const float* __restrict__ A1, const float* __restrict__ W1p,
    const float* __restrict__ bias1, float* __restrict__ C1,
    int M, int N, int K, int relu)
{
    __shared__ alignas(16) __half As[2 * ASZH];
    __shared__ alignas(16) __half Bs[2 * BSZH];

    const float* A    = blockIdx.z ? A1    : A0;
    const float* W    = blockIdx.z ? W1p   : W0;
    const float* bias = blockIdx.z ? bias1 : bias0;
    float*       C    = blockIdx.z ? C1    : C0;

    const int tid  = threadIdx.x;
    const int lane = tid & 31;
    const int warp = tid >> 5;
    const int wm   = warp >> 2;          // 0..1
    const int wn   = warp & 3;           // 0..3
    const int g    = lane >> 2;
    const int t4   = lane & 3;
    const int mrow = wm * 64;
    const int nb   = wn * 64;

    const int bm = blockIdx.y * 128;
    const int bn = blockIdx.x * 256;
    const int nk = K >> 4;

    const unsigned As_u32 = (unsigned)__cvta_generic_to_shared(As);
    const unsigned Bs_u32 = (unsigned)__cvta_generic_to_shared(Bs);

    // ldmatrix per-lane source rows
    const int mat  = lane >> 3;
    const int mrw  = lane & 7;
    const int arow = (mat & 1) * 8 + mrw;       // row within 16-row tile
    const int acol = (mat >> 1) * 8;            // k column 0/8
    const int aidx[4] = {
        (mrow + 0 * 16 + arow) * ASTR + acol,
        (mrow + 1 * 16 + arow) * ASTR + acol,
        (mrow + 2 * 16 + arow) * ASTR + acol,
        (mrow + 3 * 16 + arow) * ASTR + acol };
    const int krow = (mat & 1) * 8 + mrw;       // k row 0..15
    const int ncol = (mat >> 1) * 8;            // n column 0/8 within pair
    const int bidx[4] = {
        krow * BSTR + nb + 0 * 16 + ncol,
        krow * BSTR + nb + 1 * 16 + ncol,
        krow * BSTR + nb + 2 * 16 + ncol,
        krow * BSTR + nb + 3 * 16 + ncol };

    float acc[4][8][4];
    #pragma unroll
    for (int mt = 0; mt < 4; mt++)
        #pragma unroll
        for (int nt = 0; nt < 8; nt++)
            #pragma unroll
            for (int i = 0; i < 4; i++) acc[mt][nt][i] = 0.f;

    // ---- stage K-tile 0 into buffer 0
    {
        #pragma unroll
        for (int i = 0; i < 2; i++) {            // A: 128x16 fp32 -> half
            const int f  = tid + (i << 8);
            const int m  = f >> 2;
            const int kq = (f & 3) << 2;
            const float4 v = *(const float4*)&A[(size_t)(bm + m) * K + kq];
            uint2 p; p.x = pack_h2(v.x, v.y); p.y = pack_h2(v.z, v.w);
            *(uint2*)(As + m * ASTR + kq) = p;
        }
        #pragma unroll
        for (int i = 0; i < 4; i++) {            // B: 16x256 fp32 -> half
            const int f  = tid + (i << 8);
            const int kk = f >> 6;
            const int n  = (f & 63) << 2;
            const float4 u = *(const float4*)&W[(size_t)kk * N + bn + n];
            uint2 p; p.x = pack_h2(u.x, u.y); p.y = pack_h2(u.z, u.w);
            *(uint2*)(Bs + kk * BSTR + n) = p;
        }
    }
    __syncthreads();

    for (int kt = 0; kt < nk; kt++) {
        const int cur = kt & 1;
        const bool pf = (kt + 1 < nk);
        float4 av[2], bv[4];
        if (pf) {
            const int k0n = (kt + 1) << 4;
            #pragma unroll
            for (int i = 0; i < 2; i++) {
                const int f = tid + (i << 8);
                av[i] = *(const float4*)&A[(size_t)(bm + (f >> 2)) * K + k0n + ((f & 3) << 2)];
            }
            #pragma unroll
            for (int i = 0; i < 4; i++) {
                const int f = tid + (i << 8);
                bv[i] = *(const float4*)&W[(size_t)(k0n + (f >> 6)) * N + bn + ((f & 63) << 2)];
            }
        }

        // ---- fragments via ldmatrix
        const unsigned abase = As_u32 + (cur * ASZH) * 2;
        const unsigned bbase = Bs_u32 + (cur * BSZH) * 2;
        unsigned a[4][4], bq[4][4];
        #pragma unroll
        for (int mt = 0; mt < 4; mt++)
            ldsm_x4(a[mt][0], a[mt][1], a[mt][2], a[mt][3], abase + aidx[mt] * 2);
        #pragma unroll
        for (int pr = 0; pr < 4; pr++)
            ldsm_x4_t(bq[pr][0], bq[pr][1], bq[pr][2], bq[pr][3], bbase + bidx[pr] * 2);

        #pragma unroll
        for (int mt = 0; mt < 4; mt++)
            #pragma unroll
            for (int nt = 0; nt < 8; nt++) {
                const int pr = nt >> 1, sel = (nt & 1) << 1;
                mma_f16(acc[mt][nt][0], acc[mt][nt][1], acc[mt][nt][2], acc[mt][nt][3],
                        a[mt][0], a[mt][1], a[mt][2], a[mt][3],
                        bq[pr][sel], bq[pr][sel + 1]);
            }

        if (pf) {
            __half* Asn = As + (cur ^ 1) * ASZH;
            __half* Bsn = Bs + (cur ^ 1) * BSZH;
            #pragma unroll
            for (int i = 0; i < 2; i++) {
                const int f  = tid + (i << 8);
                const int m  = f >> 2;
                const int kq = (f & 3) << 2;
                uint2 p; p.x = pack_h2(av[i].x, av[i].y); p.y = pack_h2(av[i].z, av[i].w);
                *(uint2*)(Asn + m * ASTR + kq) = p;
            }
            #pragma unroll
            for (int i = 0; i < 4; i++) {
                const int f  = tid + (i << 8);
                const int kk = f >> 6;
                const int n  = (f & 63) << 2;
                uint2 p; p.x = pack_h2(bv[i].x, bv[i].y); p.y = pack_h2(bv[i].z, bv[i].w);
                *(uint2*)(Bsn + kk * BSTR + n) = p;
            }
        }
        __syncthreads();
    }

    // ---- epilogue: bias (+ReLU)
    #pragma unroll
    for (int mt = 0; mt < 4; mt++) {
        const int r = bm + mrow + mt * 16 + g;
        #pragma unroll
        for (int nt = 0; nt < 8; nt++) {
            const int c = bn + nb + nt * 8 + 2 * t4;
            const float b0 = bias[c], b1 = bias[c + 1];
            float v0 = acc[mt][nt][0] + b0;
            float v1 = acc[mt][nt][1] + b1;
            float v2 = acc[mt][nt][2] + b0;
            float v3 = acc[mt][nt][3] + b1;
            if (relu) {
                v0 = fmaxf(v0, 0.f); v1 = fmaxf(v1, 0.f);
                v2 = fmaxf(v2, 0.f); v3 = fmaxf(v3, 0.f);
            }
            *(float2*)&C[(size_t)r * N + c]       = make_float2(v0, v1);
            *(float2*)&C[(size_t)(r + 8) * N + c] = make_float2(v2, v3);
        }
    }
}

// ---------------------------------------------------------------------------
// Tensor-core flash attention (tf32): q-tile 128, warp owns 16 rows x 64 kv.
// Softmax in registers (quad shuffles); P relayout via warp-private smem rows.
// Q is pre-scaled by 1/sqrt(dk) at staging.
// ---------------------------------------------------------------------------
constexpr int SS_STR = 68;
constexpr int KS_STR = 36;
constexpr int VS_STR = 40;
constexpr int SS_OFF = 0;
constexpr int KS_OFF = 128 * SS_STR;
constexpr int VS_OFF = KS_OFF + 64 * KS_STR;
constexpr int ATTN_SMEM_BYTES = (VS_OFF + 64 * VS_STR) * 4;  // 54272

__global__ __launch_bounds__(256) void attn_tc(
    const float* __restrict__ QK, const float* __restrict__ Vp,
    float* __restrict__ O, int strict)
{
    extern __shared__ float sm[];
    float* Ssm = sm + SS_OFF;
    float* Ksm = sm + KS_OFF;
    float* Vsm = sm + VS_OFF;

    const int qt = blockIdx.x;
    const int bh = blockIdx.y;
    const int b  = bh >> 3;
    const int h  = bh & 7;
    const int q0 = qt << 7;
    const int t    = threadIdx.x;
    const int lane = t & 31;
    const int warp = t >> 5;
    const int m0   = warp << 4;
    const int g    = lane >> 2;
    const int t4   = lane & 3;

    const size_t base = (size_t)(b * S_) * D_ + h * DK_;

    for (int i = t; i < 1024; i += 256) {
        const int r = i >> 3, c = (i & 7) << 2;
        float4 v = *(const float4*)&QK[base + (size_t)(q0 + r) * D_ + c];
        Ssm[r * SS_STR + c + 0] = f2tf32(v.x * SCALE_);
        Ssm[r * SS_STR + c + 1] = f2tf32(v.y * SCALE_);
        Ssm[r * SS_STR + c + 2] = f2tf32(v.z * SCALE_);
        Ssm[r * SS_STR + c + 3] = f2tf32(v.w * SCALE_);
    }
    __syncthreads();
    unsigned qf[4][4];
    #pragma unroll
    for (int ks = 0; ks < 4; ks++) {
        const int k = ks * 8;
        qf[ks][0] = __float_as_uint(Ssm[(m0 + g) * SS_STR + k + t4]);
        qf[ks][1] = __float_as_uint(Ssm[(m0 + g + 8) * SS_STR + k + t4]);
        qf[ks][2] = __float_as_uint(Ssm[(m0 + g) * SS_STR + k + t4 + 4]);
        qf[ks][3] = __float_as_uint(Ssm[(m0 + g + 8) * SS_STR + k + t4 + 4]);
    }

    float acc_o[4][4];
    #pragma unroll
    for (int nt = 0; nt < 4; nt++)
        #pragma unroll
        for (int i = 0; i < 4; i++) acc_o[nt][i] = 0.f;
    float mrow[2] = { -1e30f, -1e30f };
    float lrow[2] = { 0.f, 0.f };

    const int rg  = q0 + m0 + g - strict;
    const int rg8 = rg + 8;
    const int ktmax = 2 * qt + 1;

    for (int kt = 0; kt <= ktmax; kt++) {
        const int k0 = kt << 6;
        __syncthreads();
        for (int i = t; i < 512; i += 256) {
            const int rr = i >> 3, c = (i & 7) << 2;
            float4 kv = *(const float4*)&QK[base + (size_t)(k0 + rr) * D_ + c];
            Ksm[rr * KS_STR + c + 0] = f2tf32(kv.x);
            Ksm[rr * KS_STR + c + 1] = f2tf32(kv.y);
            Ksm[rr * KS_STR + c + 2] = f2tf32(kv.z);
            Ksm[rr * KS_STR + c + 3] = f2tf32(kv.w);
            float4 vv = *(const float4*)&Vp[base + (size_t)(k0 + rr) * D_ + c];
            Vsm[rr * VS_STR + c + 0] = f2tf32(vv.x);
            Vsm[rr * VS_STR + c + 1] = f2tf32(vv.y);
            Vsm[rr * VS_STR + c + 2] = f2tf32(vv.z);
            Vsm[rr * VS_STR + c + 3] = f2tf32(vv.w);
        }
        __syncthreads();

        float s[8][4];
        #pragma unroll
        for (int nt = 0; nt < 8; nt++)
            #pragma unroll
            for (int i = 0; i < 4; i++) s[nt][i] = 0.f;
        #pragma unroll
        for (int ks = 0; ks < 4; ks++) {
            const int kb = ks * 8;
            #pragma unroll
            for (int nt = 0; nt < 8; nt++) {
                const float* Kp = &Ksm[(nt * 8 + g) * KS_STR + kb + t4];
                unsigned b0 = __float_as_uint(Kp[0]);
                unsigned b1 = __float_as_uint(Kp[4]);
                mma_tf32(s[nt][0], s[nt][1], s[nt][2], s[nt][3],
                         qf[ks][0], qf[ks][1], qf[ks][2], qf[ks][3], b0, b1);
            }
        }

        #pragma unroll
        for (int nt = 0; nt < 8; nt++) {
            const int c0c = k0 + nt * 8 + 2 * t4;
            const int c1c = c0c + 1;
            s[nt][0] = (c0c <= rg ) ? s[nt][0] : -1e30f;
            s[nt][1] = (c1c <= rg ) ? s[nt][1] : -1e30f;
            s[nt][2] = (c0c <= rg8) ? s[nt][2] : -1e30f;
            s[nt][3] = (c1c <= rg8) ? s[nt][3] : -1e30f;
        }

        float mx0 = -1e30f, mx1 = -1e30f;
        #pragma unroll
        for (int nt = 0; nt < 8; nt++) {
            mx0 = fmaxf(mx0, fmaxf(s[nt][0], s[nt][1]));
            mx1 = fmaxf(mx1, fmaxf(s[nt][2], s[nt][3]));
        }
        mx0 = fmaxf(mx0, __shfl_xor_sync(0xffffffffu, mx0, 1));
        mx0 = fmaxf(mx0, __shfl_xor_sync(0xffffffffu, mx0, 2));
        mx1 = fmaxf(mx1, __shfl_xor_sync(0xffffffffu, mx1, 1));
        mx1 = fmaxf(mx1, __shfl_xor_sync(0xffffffffu, mx1, 2));
        const float nm0 = fmaxf(mrow[0], mx0);
        const float nm1 = fmaxf(mrow[1], mx1);
        const float cr0 = __expf(mrow[0] - nm0);
        const float cr1 = __expf(mrow[1] - nm1);

        float ps0 = 0.f, ps1 = 0.f;
        #pragma unroll
        for (int nt = 0; nt < 8; nt++) {
            const float p0 = (s[nt][0] > -1e29f) ? f2tf32(__expf(s[nt][0] - nm0)) : 0.f;
            const float p1 = (s[nt][1] > -1e29f) ? f2tf32(__expf(s[nt][1] - nm0)) : 0.f;
            const float p2 = (s[nt][2] > -1e29f) ? f2tf32(__expf(s[nt][2] - nm1)) : 0.f;
            const float p3 = (s[nt][3] > -1e29f) ? f2tf32(__expf(s[nt][3] - nm1)) : 0.f;
            ps0 += p0 + p1;
            ps1 += p2 + p3;
            const int cl = nt * 8 + 2 * t4;
            *(float2*)&Ssm[(m0 + g) * SS_STR + cl]     = make_float2(p0, p1);
            *(float2*)&Ssm[(m0 + g + 8) * SS_STR + cl] = make_float2(p2, p3);
        }
        ps0 += __shfl_xor_sync(0xffffffffu, ps0, 1);
        ps0 += __shfl_xor_sync(0xffffffffu, ps0, 2);
        ps1 += __shfl_xor_sync(0xffffffffu, ps1, 1);
        ps1 += __shfl_xor_sync(0xffffffffu, ps1, 2);
        lrow[0] = lrow[0] * cr0 + ps0;
        lrow[1] = lrow[1] * cr1 + ps1;
        mrow[0] = nm0;
        mrow[1] = nm1;
        __syncwarp();

        #pragma unroll
        for (int nt = 0; nt < 4; nt++) {
            acc_o[nt][0] *= cr0; acc_o[nt][1] *= cr0;
            acc_o[nt][2] *= cr1; acc_o[nt][3] *= cr1;
        }
        #pragma unroll
        for (int kk = 0; kk < 8; kk++) {
            const int kb = kk * 8;
            unsigned a0 = __float_as_uint(Ssm[(m0 + g) * SS_STR + kb + t4]);
            unsigned a1 = __float_as_uint(Ssm[(m0 + g + 8) * SS_STR + kb + t4]);
            unsigned a2 = __float_as_uint(Ssm[(m0 + g) * SS_STR + kb + t4 + 4]);
            unsigned a3 = __float_as_uint(Ssm[(m0 + g + 8) * SS_STR + kb + t4 + 4]);
            #pragma unroll
            for (int nt = 0; nt < 4; nt++) {
                const float* Vpp = &Vsm[(kb + t4) * VS_STR + nt * 8 + g];
                unsigned b0 = __float_as_uint(Vpp[0]);
                unsigned b1 = __float_as_uint(Vpp[4 * VS_STR]);
                mma_tf32(acc_o[nt][0], acc_o[nt][1], acc_o[nt][2], acc_o[nt][3],
                         a0, a1, a2, a3, b0, b1);
            }
        }
    }

    const float i0 = (lrow[0] > 0.f) ? 1.f / lrow[0] : 0.f;
    const float i1 = (lrow[1] > 0.f) ? 1.f / lrow[1] : 0.f;
    const int row = q0 + m0 + g;
    #pragma unroll
    for (int nt = 0; nt < 4; nt++) {
        const int c = nt * 8 + 2 * t4;
        *(float2*)&O[base + (size_t)row * D_ + c] =
            make_float2(acc_o[nt][0] * i0, acc_o[nt][1] * i0);
        *(float2*)&O[base + (size_t)(row + 8) * D_ + c] =
            make_float2(acc_o[nt][2] * i1, acc_o[nt][3] * i1);
    }
}

// ---------------------------------------------------------------------------
// Fused residual add + LayerNorm: warp-per-row (256 floats, 8 per lane).
// ---------------------------------------------------------------------------
__global__ __launch_bounds__(256) void add_ln_kernel(
    const float* __restrict__ X, const float* __restrict__ R,
    const float* __restrict__ gam, const float* __restrict__ bet,
    float* __restrict__ O)
{
    const int warp = threadIdx.x >> 5;
    const int lane = threadIdx.x & 31;
    const int row  = blockIdx.x * 8 + warp;
    const size_t off = (size_t)row * D_ + lane * 8;

    float4 x0 = *(const float4*)&X[off];
    float4 x1 = *(const float4*)&X[off + 4];
    float4 r0 = *(const float4*)&R[off];
    float4 r1 = *(const float4*)&R[off + 4];
    float v[8] = { x0.x + r0.x, x0.y + r0.y, x0.z + r0.z, x0.w + r0.w,
                   x1.x + r1.x, x1.y + r1.y, x1.z + r1.z, x1.w + r1.w };

    float s = 0.f;
    #pragma unroll
    for (int i = 0; i < 8; i++) s += v[i];
    #pragma unroll
    for (int o = 16; o > 0; o >>= 1) s += __shfl_xor_sync(0xffffffffu, s, o);
    const float mu = s * (1.f / 256.f);

    float s2 = 0.f;
    #pragma unroll
    for (int i = 0; i < 8; i++) { v[i] -= mu; s2 += v[i] * v[i]; }
    #pragma unroll
    for (int o = 16; o > 0; o >>= 1) s2 += __shfl_xor_sync(0xffffffffu, s2, o);
    const float rs = rsqrtf(s2 * (1.f / 256.f) + 1e-5f);

    const int c = lane * 8;
    float4 ga = *(const float4*)&gam[c];
    float4 gb = *(const float4*)&gam[c + 4];
    float4 ba = *(const float4*)&bet[c];
    float4 bb = *(const float4*)&bet[c + 4];

    float4 oa = make_float4(v[0] * rs * ga.x + ba.x, v[1] * rs * ga.y + ba.y,
                            v[2] * rs * ga.z + ba.z, v[3] * rs * ga.w + ba.w);
    float4 ob = make_float4(v[4] * rs * gb.x + bb.x, v[5] * rs * gb.y + bb.y,
                            v[6] * rs * gb.z + bb.z, v[7] * rs * gb.w + bb.w);
    *(float4*)&O[off]     = oa;
    *(float4*)&O[off + 4] = ob;
}

// ---------------------------------------------------------------------------
// Host-side orchestration
// ---------------------------------------------------------------------------
struct Scratch { float *y, *x, *kp, *vp, *att, *o, *x1, *f, *h; };

static void launch_layer(const float* Qin, const float* Vin, float* Out,
                         int li, int strict, int apply_pos,
                         void* const* d_in, const Scratch& P)
{
    const float* Wk  = (const float*)d_in[2]  + (size_t)li * D_ * D_;
    const float* bk  = (const float*)d_in[3]  + (size_t)li * D_;
    const float* Wv  = (const float*)d_in[4]  + (size_t)li * D_ * D_;
    const float* bv  = (const float*)d_in[5]  + (size_t)li * D_;
    const float* Wo  = (const float*)d_in[6]  + (size_t)li * D_ * D_;
    const float* bo  = (const float*)d_in[7]  + (size_t)li * D_;
    const float* g1  = (const float*)d_in[8]  + (size_t)li * D_;
    const float* be1 = (const float*)d_in[9]  + (size_t)li * D_;
    const float* W1  = (const float*)d_in[10] + (size_t)li * D_ * DFF_;
    const float* bf1 = (const float*)d_in[11] + (size_t)li * DFF_;
    const float* W2  = (const float*)d_in[12] + (size_t)li * DFF_ * D_;
    const float* bf2 = (const float*)d_in[13] + (size_t)li * D_;
    const float* g2  = (const float*)d_in[14] + (size_t)li * D_;
    const float* be2 = (const float*)d_in[15] + (size_t)li * D_;

    // merged K-proj (set0) + V-proj (set1) via blockIdx.z
    gemm_tc<<<dim3(D_ / 256, BS_ / 128, 2), 256>>>(
        Qin, Wk, bk, P.kp, Vin, Wv, bv, P.vp, BS_, D_, D_, 0);
    attn_tc<<<dim3(S_ / 128, B_ * H_), 256, ATTN_SMEM_BYTES>>>(P.kp, P.vp, P.att, strict);
    gemm_tc<<<dim3(D_ / 256, BS_ / 128, 1), 256>>>(
        P.att, Wo, bo, P.o, P.att, Wo, bo, P.o, BS_, D_, D_, 0);

    float* ln1out = apply_pos ? P.x1 : Out;
    add_ln_kernel<<<BS_ / 8, 256>>>(Qin, P.o, g1, be1, ln1out);

    if (apply_pos) {
        gemm_tc<<<dim3(DFF_ / 256, BS_ / 128, 1), 256>>>(
            P.x1, W1, bf1, P.h, P.x1, W1, bf1, P.h, BS_, DFF_, D_, 1);
        gemm_tc<<<dim3(D_ / 256, BS_ / 128, 1), 256>>>(
            P.h, W2, bf2, P.f, P.h, W2, bf2, P.f, BS_, D_, DFF_, 0);
        add_ln_kernel<<<BS_ / 8, 256>>>(P.x1, P.f, g2, be2, Out);
    }
}

extern "C" void kernel_launch(void* const* d_in, const int* in_sizes, int n_in,
                              void* d_out, int out_size)
{
    (void)in_sizes; (void)n_in; (void)out_size;
    const float* qe = (const float*)d_in[0];   // q_embed_data  -> x stream
    const float* qa = (const float*)d_in[1];   // qa_embed_data -> y stream

    static bool attr_done = false;
    if (!attr_done) {
        cudaFuncSetAttribute(attn_tc, cudaFuncAttributeMaxDynamicSharedMemorySize,
                             ATTN_SMEM_BYTES);
        attr_done = true;
    }

    Scratch P;
    cudaGetSymbolAddress((void**)&P.y,  g_y);
    cudaGetSymbolAddress((void**)&P.x,  g_x);
    cudaGetSymbolAddress((void**)&P.kp, g_kp);
    cudaGetSymbolAddress((void**)&P.vp, g_vp);
    cudaGetSymbolAddress((void**)&P.att, g_att);
    cudaGetSymbolAddress((void**)&P.o,  g_o);
    cudaGetSymbolAddress((void**)&P.x1, g_x1);
    cudaGetSymbolAddress((void**)&P.f,  g_f);
    cudaGetSymbolAddress((void**)&P.h,  g_h);

    // Encoder blocks (y = qa stream), mask incl. diagonal, with FFN
    launch_layer(qa,  qa,  P.y, 0, /*strict=*/0, /*apply_pos=*/1, d_in, P);
    launch_layer(P.y, P.y, P.y, 1, 0, 1, d_in, P);

    // Decoder blocks on x stream
    launch_layer(qe,  qe,  P.x, 2, /*strict=*/0, /*apply_pos=*/0, d_in, P);   // self, no FFN
    launch_layer(P.x, P.y, P.x, 3, /*strict=*/1, /*apply_pos=*/1, d_in, P);   // cross (V=y)
    launch_layer(P.x, P.x, P.x, 4, 0, 0, d_in, P);                            // self, no FFN
    launch_layer(P.x, P.y, (float*)d_out, 5, 1, 1, d_in, P);                  // cross -> out
}

// round 9
// speedup vs baseline: 2.0275x; 1.1017x over previous
#include <cuda_runtime.h>
#include <cuda_fp16.h>
#include <math.h>

// Problem dims (fixed by the reference)
constexpr int B_   = 64;
constexpr int S_   = 512;
constexpr int D_   = 256;
constexpr int H_   = 8;
constexpr int DK_  = 32;
constexpr int DFF_ = 1024;
constexpr int BS_  = B_ * S_;          // 32768 rows
constexpr float SCALE_ = 0.17677669529663687f; // 1/sqrt(32)

// ---------------------------------------------------------------------------
// Scratch (no allocations allowed -> __device__ globals)
// ---------------------------------------------------------------------------
__device__ float g_y  [BS_ * D_];
__device__ float g_x  [BS_ * D_];
__device__ float g_kp [BS_ * D_];
__device__ float g_vp [BS_ * D_];
__device__ float g_att[BS_ * D_];
__device__ float g_o  [BS_ * D_];
__device__ float g_x1 [BS_ * D_];
__device__ float g_f  [BS_ * D_];
__device__ float g_h  [BS_ * DFF_];

// ---------------------------------------------------------------------------
// helpers
// ---------------------------------------------------------------------------
__device__ __forceinline__ unsigned pack_h2(float lo, float hi) {
    unsigned u;
    asm("cvt.rn.f16x2.f32 %0, %1, %2;" : "=r"(u) : "f"(hi), "f"(lo));
    return u;
}

__device__ __forceinline__ void mma_f16(
    float& c0, float& c1, float& c2, float& c3,
    unsigned a0, unsigned a1, unsigned a2, unsigned a3,
    unsigned b0, unsigned b1)
{
    asm volatile(
        "mma.sync.aligned.m16n8k16.row.col.f32.f16.f16.f32 "
        "{%0,%1,%2,%3}, {%4,%5,%6,%7}, {%8,%9}, {%0,%1,%2,%3};\n"
        : "+f"(c0), "+f"(c1), "+f"(c2), "+f"(c3)
        : "r"(a0), "r"(a1), "r"(a2), "r"(a3), "r"(b0), "r"(b1));
}

__device__ __forceinline__ void ldsm_x4(
    unsigned& r0, unsigned& r1, unsigned& r2, unsigned& r3, unsigned addr)
{
    asm volatile("ldmatrix.sync.aligned.m8n8.x4.shared.b16 {%0,%1,%2,%3}, [%4];"
                 : "=r"(r0), "=r"(r1), "=r"(r2), "=r"(r3) : "r"(addr));
}

__device__ __forceinline__ void ldsm_x4_t(
    unsigned& r0, unsigned& r1, unsigned& r2, unsigned& r3, unsigned addr)
{
    asm volatile("ldmatrix.sync.aligned.m8n8.x4.trans.shared.b16 {%0,%1,%2,%3}, [%4];"
                 : "=r"(r0), "=r"(r1), "=r"(r2), "=r"(r3) : "r"(addr));
}

// ---------------------------------------------------------------------------
// fp16 tensor-core GEMM, double-buffered, ldmatrix fragments.
// Block 128x256, BK=16, 256 threads = 8 warps (2x4), warp tile 64x64.
// fp32 accum; blockIdx.z selects operand set (merged K/V projection launch).
// ---------------------------------------------------------------------------
constexpr int ASTR = 40;                 // halves
constexpr int BSTR = 264;                // halves
constexpr int ASZH = 128 * ASTR;         // 5120 halves / stage
constexpr int BSZH = 16 * BSTR;          // 4224 halves / stage

__global__ __launch_bounds__(256, 1) void gemm_tc(
    const float* __restrict__ A0, const float* __restrict__ W0,
    const float* __restrict__ bias0, float* __restrict__ C0,
    const float* __restrict__ A1, const float* __restrict__ W1p,
    const float* __restrict__ bias1, float* __restrict__ C1,
    int M, int N, int K, int relu)
{
    __shared__ alignas(16) __half As[2 * ASZH];
    __shared__ alignas(16) __half Bs[2 * BSZH];

    const float* A    = blockIdx.z ? A1    : A0;
    const float* W    = blockIdx.z ? W1p   : W0;
    const float* bias = blockIdx.z ? bias1 : bias0;
    float*       C    = blockIdx.z ? C1    : C0;

    const int tid  = threadIdx.x;
    const int lane = tid & 31;
    const int warp = tid >> 5;
    const int wm   = warp >> 2;
    const int wn   = warp & 3;
    const int g    = lane >> 2;
    const int t4   = lane & 3;
    const int mrow = wm * 64;
    const int nb   = wn * 64;

    const int bm = blockIdx.y * 128;
    const int bn = blockIdx.x * 256;
    const int nk = K >> 4;

    const unsigned As_u32 = (unsigned)__cvta_generic_to_shared(As);
    const unsigned Bs_u32 = (unsigned)__cvta_generic_to_shared(Bs);

    const int mat  = lane >> 3;
    const int mrw  = lane & 7;
    const int arow = (mat & 1) * 8 + mrw;
    const int acol = (mat >> 1) * 8;
    const int aidx[4] = {
        (mrow + 0 * 16 + arow) * ASTR + acol,
        (mrow + 1 * 16 + arow) * ASTR + acol,
        (mrow + 2 * 16 + arow) * ASTR + acol,
        (mrow + 3 * 16 + arow) * ASTR + acol };
    const int krow = (mat & 1) * 8 + mrw;
    const int ncol = (mat >> 1) * 8;
    const int bidx[4] = {
        krow * BSTR + nb + 0 * 16 + ncol,
        krow * BSTR + nb + 1 * 16 + ncol,
        krow * BSTR + nb + 2 * 16 + ncol,
        krow * BSTR + nb + 3 * 16 + ncol };

    float acc[4][8][4];
    #pragma unroll
    for (int mt = 0; mt < 4; mt++)
        #pragma unroll
        for (int nt = 0; nt < 8; nt++)
            #pragma unroll
            for (int i = 0; i < 4; i++) acc[mt][nt][i] = 0.f;

    {
        #pragma unroll
        for (int i = 0; i < 2; i++) {
            const int f  = tid + (i << 8);
            const int m  = f >> 2;
            const int kq = (f & 3) << 2;
            const float4 v = *(const float4*)&A[(size_t)(bm + m) * K + kq];
            uint2 p; p.x = pack_h2(v.x, v.y); p.y = pack_h2(v.z, v.w);
            *(uint2*)(As + m * ASTR + kq) = p;
        }
        #pragma unroll
        for (int i = 0; i < 4; i++) {
            const int f  = tid + (i << 8);
            const int kk = f >> 6;
            const int n  = (f & 63) << 2;
            const float4 u = *(const float4*)&W[(size_t)kk * N + bn + n];
            uint2 p; p.x = pack_h2(u.x, u.y); p.y = pack_h2(u.z, u.w);
            *(uint2*)(Bs + kk * BSTR + n) = p;
        }
    }
    __syncthreads();

    for (int kt = 0; kt < nk; kt++) {
        const int cur = kt & 1;
        const bool pf = (kt + 1 < nk);
        float4 av[2], bv[4];
        if (pf) {
            const int k0n = (kt + 1) << 4;
            #pragma unroll
            for (int i = 0; i < 2; i++) {
                const int f = tid + (i << 8);
                av[i] = *(const float4*)&A[(size_t)(bm + (f >> 2)) * K + k0n + ((f & 3) << 2)];
            }
            #pragma unroll
            for (int i = 0; i < 4; i++) {
                const int f = tid + (i << 8);
                bv[i] = *(const float4*)&W[(size_t)(k0n + (f >> 6)) * N + bn + ((f & 63) << 2)];
            }
        }

        const unsigned abase = As_u32 + (cur * ASZH) * 2;
        const unsigned bbase = Bs_u32 + (cur * BSZH) * 2;
        unsigned a[4][4], bq[4][4];
        #pragma unroll
        for (int mt = 0; mt < 4; mt++)
            ldsm_x4(a[mt][0], a[mt][1], a[mt][2], a[mt][3], abase + aidx[mt] * 2);
        #pragma unroll
        for (int pr = 0; pr < 4; pr++)
            ldsm_x4_t(bq[pr][0], bq[pr][1], bq[pr][2], bq[pr][3], bbase + bidx[pr] * 2);

        #pragma unroll
        for (int mt = 0; mt < 4; mt++)
            #pragma unroll
            for (int nt = 0; nt < 8; nt++) {
                const int pr = nt >> 1, sel = (nt & 1) << 1;
                mma_f16(acc[mt][nt][0], acc[mt][nt][1], acc[mt][nt][2], acc[mt][nt][3],
                        a[mt][0], a[mt][1], a[mt][2], a[mt][3],
                        bq[pr][sel], bq[pr][sel + 1]);
            }

        if (pf) {
            __half* Asn = As + (cur ^ 1) * ASZH;
            __half* Bsn = Bs + (cur ^ 1) * BSZH;
            #pragma unroll
            for (int i = 0; i < 2; i++) {
                const int f  = tid + (i << 8);
                const int m  = f >> 2;
                const int kq = (f & 3) << 2;
                uint2 p; p.x = pack_h2(av[i].x, av[i].y); p.y = pack_h2(av[i].z, av[i].w);
                *(uint2*)(Asn + m * ASTR + kq) = p;
            }
            #pragma unroll
            for (int i = 0; i < 4; i++) {
                const int f  = tid + (i << 8);
                const int kk = f >> 6;
                const int n  = (f & 63) << 2;
                uint2 p; p.x = pack_h2(bv[i].x, bv[i].y); p.y = pack_h2(bv[i].z, bv[i].w);
                *(uint2*)(Bsn + kk * BSTR + n) = p;
            }
        }
        __syncthreads();
    }

    #pragma unroll
    for (int mt = 0; mt < 4; mt++) {
        const int r = bm + mrow + mt * 16 + g;
        #pragma unroll
        for (int nt = 0; nt < 8; nt++) {
            const int c = bn + nb + nt * 8 + 2 * t4;
            const float b0 = bias[c], b1 = bias[c + 1];
            float v0 = acc[mt][nt][0] + b0;
            float v1 = acc[mt][nt][1] + b1;
            float v2 = acc[mt][nt][2] + b0;
            float v3 = acc[mt][nt][3] + b1;
            if (relu) {
                v0 = fmaxf(v0, 0.f); v1 = fmaxf(v1, 0.f);
                v2 = fmaxf(v2, 0.f); v3 = fmaxf(v3, 0.f);
            }
            *(float2*)&C[(size_t)r * N + c]       = make_float2(v0, v1);
            *(float2*)&C[(size_t)(r + 8) * N + c] = make_float2(v2, v3);
        }
    }
}

// ---------------------------------------------------------------------------
// fp16 tensor-core flash attention: q-tile 128, warp owns 16 rows x 64 kv.
// m16n8k16 mma via ldmatrix; softmax fp32 in registers (quad shuffles);
// P packed to half at store, warp-private rows (syncwarp only).
// Static smem: Q[128x40] K[64x40] V[64x40] P[128x72] halves = 38912 B.
// ---------------------------------------------------------------------------
constexpr int QSTR = 40;
constexpr int KSTR = 40;
constexpr int VSTR = 40;
constexpr int PSTR = 72;

__global__ __launch_bounds__(256) void attn_tc(
    const float* __restrict__ QK, const float* __restrict__ Vp,
    float* __restrict__ O, int strict)
{
    __shared__ alignas(16) __half Qs[128 * QSTR];
    __shared__ alignas(16) __half Ks[64 * KSTR];
    __shared__ alignas(16) __half Vs[64 * VSTR];
    __shared__ alignas(16) __half Ps[128 * PSTR];

    const int qt = blockIdx.x;
    const int bh = blockIdx.y;
    const int b  = bh >> 3;
    const int h  = bh & 7;
    const int q0 = qt << 7;
    const int t    = threadIdx.x;
    const int lane = t & 31;
    const int warp = t >> 5;
    const int m0   = warp << 4;
    const int g    = lane >> 2;
    const int t4   = lane & 3;
    const int mat  = lane >> 3;
    const int mrw  = lane & 7;
    const int arow = (mat & 1) * 8 + mrw;    // A-frag row-in-16
    const int acol = (mat >> 1) * 8;         // A-frag k col 0/8

    const unsigned Qs_u = (unsigned)__cvta_generic_to_shared(Qs);
    const unsigned Ks_u = (unsigned)__cvta_generic_to_shared(Ks);
    const unsigned Vs_u = (unsigned)__cvta_generic_to_shared(Vs);
    const unsigned Ps_u = (unsigned)__cvta_generic_to_shared(Ps);

    const size_t base = (size_t)(b * S_) * D_ + h * DK_;

    // ---- stage Q (128 x 32), pre-scaled, fp32 -> half
    for (int i = t; i < 1024; i += 256) {
        const int r = i >> 3, c = (i & 7) << 2;
        float4 v = *(const float4*)&QK[base + (size_t)(q0 + r) * D_ + c];
        uint2 p;
        p.x = pack_h2(v.x * SCALE_, v.y * SCALE_);
        p.y = pack_h2(v.z * SCALE_, v.w * SCALE_);
        *(uint2*)(Qs + r * QSTR + c) = p;
    }
    __syncthreads();

    // Q a-frags: 2 k-steps of 16
    unsigned qf[2][4];
    #pragma unroll
    for (int ks = 0; ks < 2; ks++)
        ldsm_x4(qf[ks][0], qf[ks][1], qf[ks][2], qf[ks][3],
                Qs_u + ((m0 + arow) * QSTR + ks * 16 + acol) * 2);

    float acc_o[4][4];
    #pragma unroll
    for (int nt = 0; nt < 4; nt++)
        #pragma unroll
        for (int i = 0; i < 4; i++) acc_o[nt][i] = 0.f;
    float mrowv[2] = { -1e30f, -1e30f };
    float lrow[2] = { 0.f, 0.f };

    const int rg  = q0 + m0 + g - strict;
    const int rg8 = rg + 8;
    const int ktmax = 2 * qt + 1;

    for (int kt = 0; kt <= ktmax; kt++) {
        const int k0 = kt << 6;
        __syncthreads();
        for (int i = t; i < 512; i += 256) {
            const int rr = i >> 3, c = (i & 7) << 2;
            float4 kv = *(const float4*)&QK[base + (size_t)(k0 + rr) * D_ + c];
            uint2 pk; pk.x = pack_h2(kv.x, kv.y); pk.y = pack_h2(kv.z, kv.w);
            *(uint2*)(Ks + rr * KSTR + c) = pk;
            float4 vv = *(const float4*)&Vp[base + (size_t)(k0 + rr) * D_ + c];
            uint2 pv; pv.x = pack_h2(vv.x, vv.y); pv.y = pack_h2(vv.z, vv.w);
            *(uint2*)(Vs + rr * VSTR + c) = pv;
        }
        __syncthreads();

        // ---- scores: warp 16 x 64 via m16n8k16
        float s[8][4];
        #pragma unroll
        for (int nt = 0; nt < 8; nt++)
            #pragma unroll
            for (int i = 0; i < 4; i++) s[nt][i] = 0.f;
        #pragma unroll
        for (int ks = 0; ks < 2; ks++) {
            const int kb = ks * 16;
            #pragma unroll
            for (int np = 0; np < 4; np++) {
                unsigned bq0, bq1, bq2, bq3;
                // K stored [n][k]: non-trans ldmatrix gives col-major B frag
                ldsm_x4(bq0, bq1, bq2, bq3,
                        Ks_u + ((np * 16 + (mat >> 1) * 8 + mrw) * KSTR + kb + (mat & 1) * 8) * 2);
                mma_f16(s[np*2][0], s[np*2][1], s[np*2][2], s[np*2][3],
                        qf[ks][0], qf[ks][1], qf[ks][2], qf[ks][3], bq0, bq1);
                mma_f16(s[np*2+1][0], s[np*2+1][1], s[np*2+1][2], s[np*2+1][3],
                        qf[ks][0], qf[ks][1], qf[ks][2], qf[ks][3], bq2, bq3);
            }
        }

        // ---- mask (register)
        #pragma unroll
        for (int nt = 0; nt < 8; nt++) {
            const int c0c = k0 + nt * 8 + 2 * t4;
            const int c1c = c0c + 1;
            s[nt][0] = (c0c <= rg ) ? s[nt][0] : -1e30f;
            s[nt][1] = (c1c <= rg ) ? s[nt][1] : -1e30f;
            s[nt][2] = (c0c <= rg8) ? s[nt][2] : -1e30f;
            s[nt][3] = (c1c <= rg8) ? s[nt][3] : -1e30f;
        }

        // ---- row max (register + quad shuffle)
        float mx0 = -1e30f, mx1 = -1e30f;
        #pragma unroll
        for (int nt = 0; nt < 8; nt++) {
            mx0 = fmaxf(mx0, fmaxf(s[nt][0], s[nt][1]));
            mx1 = fmaxf(mx1, fmaxf(s[nt][2], s[nt][3]));
        }
        mx0 = fmaxf(mx0, __shfl_xor_sync(0xffffffffu, mx0, 1));
        mx0 = fmaxf(mx0, __shfl_xor_sync(0xffffffffu, mx0, 2));
        mx1 = fmaxf(mx1, __shfl_xor_sync(0xffffffffu, mx1, 1));
        mx1 = fmaxf(mx1, __shfl_xor_sync(0xffffffffu, mx1, 2));
        const float nm0 = fmaxf(mrowv[0], mx0);
        const float nm1 = fmaxf(mrowv[1], mx1);
        const float cr0 = __expf(mrowv[0] - nm0);
        const float cr1 = __expf(mrowv[1] - nm1);

        // ---- exp + pack P to half, store to warp-private smem rows
        float ps0 = 0.f, ps1 = 0.f;
        #pragma unroll
        for (int nt = 0; nt < 8; nt++) {
            const float p0 = (s[nt][0] > -1e29f) ? __expf(s[nt][0] - nm0) : 0.f;
            const float p1 = (s[nt][1] > -1e29f) ? __expf(s[nt][1] - nm0) : 0.f;
            const float p2 = (s[nt][2] > -1e29f) ? __expf(s[nt][2] - nm1) : 0.f;
            const float p3 = (s[nt][3] > -1e29f) ? __expf(s[nt][3] - nm1) : 0.f;
            ps0 += p0 + p1;
            ps1 += p2 + p3;
            const int cl = nt * 8 + 2 * t4;
            *(unsigned*)(Ps + (m0 + g) * PSTR + cl)     = pack_h2(p0, p1);
            *(unsigned*)(Ps + (m0 + g + 8) * PSTR + cl) = pack_h2(p2, p3);
        }
        ps0 += __shfl_xor_sync(0xffffffffu, ps0, 1);
        ps0 += __shfl_xor_sync(0xffffffffu, ps0, 2);
        ps1 += __shfl_xor_sync(0xffffffffu, ps1, 1);
        ps1 += __shfl_xor_sync(0xffffffffu, ps1, 2);
        lrow[0] = lrow[0] * cr0 + ps0;
        lrow[1] = lrow[1] * cr1 + ps1;
        mrowv[0] = nm0;
        mrowv[1] = nm1;
        __syncwarp();

        // ---- rescale accumulators, then PV via m16n8k16
        #pragma unroll
        for (int nt = 0; nt < 4; nt++) {
            acc_o[nt][0] *= cr0; acc_o[nt][1] *= cr0;
            acc_o[nt][2] *= cr1; acc_o[nt][3] *= cr1;
        }
        #pragma unroll
        for (int ks = 0; ks < 4; ks++) {
            const int kb = ks * 16;
            unsigned pa0, pa1, pa2, pa3;
            ldsm_x4(pa0, pa1, pa2, pa3,
                    Ps_u + ((m0 + arow) * PSTR + kb + acol) * 2);
            #pragma unroll
            for (int np = 0; np < 2; np++) {
                unsigned vb0, vb1, vb2, vb3;
                // V stored [k][n]: trans ldmatrix gives col-major B frag
                ldsm_x4_t(vb0, vb1, vb2, vb3,
                          Vs_u + ((kb + (mat & 1) * 8 + mrw) * VSTR + np * 16 + (mat >> 1) * 8) * 2);
                mma_f16(acc_o[np*2][0], acc_o[np*2][1], acc_o[np*2][2], acc_o[np*2][3],
                        pa0, pa1, pa2, pa3, vb0, vb1);
                mma_f16(acc_o[np*2+1][0], acc_o[np*2+1][1], acc_o[np*2+1][2], acc_o[np*2+1][3],
                        pa0, pa1, pa2, pa3, vb2, vb3);
            }
        }
    }

    // ---- finalize: divide by l (fully-masked row -> 0), write out
    const float i0 = (lrow[0] > 0.f) ? 1.f / lrow[0] : 0.f;
    const float i1 = (lrow[1] > 0.f) ? 1.f / lrow[1] : 0.f;
    const int row = q0 + m0 + g;
    #pragma unroll
    for (int nt = 0; nt < 4; nt++) {
        const int c = nt * 8 + 2 * t4;
        *(float2*)&O[base + (size_t)row * D_ + c] =
            make_float2(acc_o[nt][0] * i0, acc_o[nt][1] * i0);
        *(float2*)&O[base + (size_t)(row + 8) * D_ + c] =
            make_float2(acc_o[nt][2] * i1, acc_o[nt][3] * i1);
    }
}

// ---------------------------------------------------------------------------
// Fused residual add + LayerNorm: warp-per-row (256 floats, 8 per lane).
// ---------------------------------------------------------------------------
__global__ __launch_bounds__(256) void add_ln_kernel(
    const float* __restrict__ X, const float* __restrict__ R,
    const float* __restrict__ gam, const float* __restrict__ bet,
    float* __restrict__ O)
{
    const int warp = threadIdx.x >> 5;
    const int lane = threadIdx.x & 31;
    const int row  = blockIdx.x * 8 + warp;
    const size_t off = (size_t)row * D_ + lane * 8;

    float4 x0 = *(const float4*)&X[off];
    float4 x1 = *(const float4*)&X[off + 4];
    float4 r0 = *(const float4*)&R[off];
    float4 r1 = *(const float4*)&R[off + 4];
    float v[8] = { x0.x + r0.x, x0.y + r0.y, x0.z + r0.z, x0.w + r0.w,
                   x1.x + r1.x, x1.y + r1.y, x1.z + r1.z, x1.w + r1.w };

    float s = 0.f;
    #pragma unroll
    for (int i = 0; i < 8; i++) s += v[i];
    #pragma unroll
    for (int o = 16; o > 0; o >>= 1) s += __shfl_xor_sync(0xffffffffu, s, o);
    const float mu = s * (1.f / 256.f);

    float s2 = 0.f;
    #pragma unroll
    for (int i = 0; i < 8; i++) { v[i] -= mu; s2 += v[i] * v[i]; }
    #pragma unroll
    for (int o = 16; o > 0; o >>= 1) s2 += __shfl_xor_sync(0xffffffffu, s2, o);
    const float rs = rsqrtf(s2 * (1.f / 256.f) + 1e-5f);

    const int c = lane * 8;
    float4 ga = *(const float4*)&gam[c];
    float4 gb = *(const float4*)&gam[c + 4];
    float4 ba = *(const float4*)&bet[c];
    float4 bb = *(const float4*)&bet[c + 4];

    float4 oa = make_float4(v[0] * rs * ga.x + ba.x, v[1] * rs * ga.y + ba.y,
                            v[2] * rs * ga.z + ba.z, v[3] * rs * ga.w + ba.w);
    float4 ob = make_float4(v[4] * rs * gb.x + bb.x, v[5] * rs * gb.y + bb.y,
                            v[6] * rs * gb.z + bb.z, v[7] * rs * gb.w + bb.w);
    *(float4*)&O[off]     = oa;
    *(float4*)&O[off + 4] = ob;
}

// ---------------------------------------------------------------------------
// Host-side orchestration
// ---------------------------------------------------------------------------
struct Scratch { float *y, *x, *kp, *vp, *att, *o, *x1, *f, *h; };

static void launch_layer(const float* Qin, const float* Vin, float* Out,
                         int li, int strict, int apply_pos,
                         void* const* d_in, const Scratch& P)
{
    const float* Wk  = (const float*)d_in[2]  + (size_t)li * D_ * D_;
    const float* bk  = (const float*)d_in[3]  + (size_t)li * D_;
    const float* Wv  = (const float*)d_in[4]  + (size_t)li * D_ * D_;
    const float* bv  = (const float*)d_in[5]  + (size_t)li * D_;
    const float* Wo  = (const float*)d_in[6]  + (size_t)li * D_ * D_;
    const float* bo  = (const float*)d_in[7]  + (size_t)li * D_;
    const float* g1  = (const float*)d_in[8]  + (size_t)li * D_;
    const float* be1 = (const float*)d_in[9]  + (size_t)li * D_;
    const float* W1  = (const float*)d_in[10] + (size_t)li * D_ * DFF_;
    const float* bf1 = (const float*)d_in[11] + (size_t)li * DFF_;
    const float* W2  = (const float*)d_in[12] + (size_t)li * DFF_ * D_;
    const float* bf2 = (const float*)d_in[13] + (size_t)li * D_;
    const float* g2  = (const float*)d_in[14] + (size_t)li * D_;
    const float* be2 = (const float*)d_in[15] + (size_t)li * D_;

    // merged K-proj (set0) + V-proj (set1) via blockIdx.z
    gemm_tc<<<dim3(D_ / 256, BS_ / 128, 2), 256>>>(
        Qin, Wk, bk, P.kp, Vin, Wv, bv, P.vp, BS_, D_, D_, 0);
    attn_tc<<<dim3(S_ / 128, B_ * H_), 256>>>(P.kp, P.vp, P.att, strict);
    gemm_tc<<<dim3(D_ / 256, BS_ / 128, 1), 256>>>(
        P.att, Wo, bo, P.o, P.att, Wo, bo, P.o, BS_, D_, D_, 0);

    float* ln1out = apply_pos ? P.x1 : Out;
    add_ln_kernel<<<BS_ / 8, 256>>>(Qin, P.o, g1, be1, ln1out);

    if (apply_pos) {
        gemm_tc<<<dim3(DFF_ / 256, BS_ / 128, 1), 256>>>(
            P.x1, W1, bf1, P.h, P.x1, W1, bf1, P.h, BS_, DFF_, D_, 1);
        gemm_tc<<<dim3(D_ / 256, BS_ / 128, 1), 256>>>(
            P.h, W2, bf2, P.f, P.h, W2, bf2, P.f, BS_, D_, DFF_, 0);
        add_ln_kernel<<<BS_ / 8, 256>>>(P.x1, P.f, g2, be2, Out);
    }
}

extern "C" void kernel_launch(void* const* d_in, const int* in_sizes, int n_in,
                              void* d_out, int out_size)
{
    (void)in_sizes; (void)n_in; (void)out_size;
    const float* qe = (const float*)d_in[0];   // q_embed_data  -> x stream
    const float* qa = (const float*)d_in[1];   // qa_embed_data -> y stream

    Scratch P;
    cudaGetSymbolAddress((void**)&P.y,  g_y);
    cudaGetSymbolAddress((void**)&P.x,  g_x);
    cudaGetSymbolAddress((void**)&P.kp, g_kp);
    cudaGetSymbolAddress((void**)&P.vp, g_vp);
    cudaGetSymbolAddress((void**)&P.att, g_att);
    cudaGetSymbolAddress((void**)&P.o,  g_o);
    cudaGetSymbolAddress((void**)&P.x1, g_x1);
    cudaGetSymbolAddress((void**)&P.f,  g_f);
    cudaGetSymbolAddress((void**)&P.h,  g_h);

    // Encoder blocks (y = qa stream), mask incl. diagonal, with FFN
    launch_layer(qa,  qa,  P.y, 0, /*strict=*/0, /*apply_pos=*/1, d_in, P);
    launch_layer(P.y, P.y, P.y, 1, 0, 1, d_in, P);

    // Decoder blocks on x stream
    launch_layer(qe,  qe,  P.x, 2, /*strict=*/0, /*apply_pos=*/0, d_in, P);   // self, no FFN
    launch_layer(P.x, P.y, P.x, 3, /*strict=*/1, /*apply_pos=*/1, d_in, P);   // cross (V=y)
    launch_layer(P.x, P.x, P.x, 4, 0, 0, d_in, P);                            // self, no FFN
    launch_layer(P.x, P.y, (float*)d_out, 5, 1, 1, d_in, P);                  // cross -> out
}

// round 10
// speedup vs baseline: 2.0277x; 1.0001x over previous
#include <cuda_runtime.h>
#include <cuda_fp16.h>
#include <math.h>

// Problem dims (fixed by the reference)
constexpr int B_   = 64;
constexpr int S_   = 512;
constexpr int D_   = 256;
constexpr int H_   = 8;
constexpr int DK_  = 32;
constexpr int DFF_ = 1024;
constexpr int BS_  = B_ * S_;          // 32768 rows
constexpr float SCALE_ = 0.17677669529663687f; // 1/sqrt(32)

// ---------------------------------------------------------------------------
// Scratch (no allocations allowed -> __device__ globals)
// ---------------------------------------------------------------------------
__device__ float g_y  [BS_ * D_];
__device__ float g_x  [BS_ * D_];
__device__ float g_kp [BS_ * D_];
__device__ float g_vp [BS_ * D_];
__device__ float g_att[BS_ * D_];
__device__ float g_o  [BS_ * D_];
__device__ float g_x1 [BS_ * D_];
__device__ float g_f  [BS_ * D_];
__device__ float g_h  [BS_ * DFF_];

// ---------------------------------------------------------------------------
// helpers
// ---------------------------------------------------------------------------
__device__ __forceinline__ unsigned pack_h2(float lo, float hi) {
    unsigned u;
    asm("cvt.rn.f16x2.f32 %0, %1, %2;" : "=r"(u) : "f"(hi), "f"(lo));
    return u;
}

__device__ __forceinline__ void mma_f16(
    float& c0, float& c1, float& c2, float& c3,
    unsigned a0, unsigned a1, unsigned a2, unsigned a3,
    unsigned b0, unsigned b1)
{
    asm volatile(
        "mma.sync.aligned.m16n8k16.row.col.f32.f16.f16.f32 "
        "{%0,%1,%2,%3}, {%4,%5,%6,%7}, {%8,%9}, {%0,%1,%2,%3};\n"
        : "+f"(c0), "+f"(c1), "+f"(c2), "+f"(c3)
        : "r"(a0), "r"(a1), "r"(a2), "r"(a3), "r"(b0), "r"(b1));
}

__device__ __forceinline__ void ldsm_x4(
    unsigned& r0, unsigned& r1, unsigned& r2, unsigned& r3, unsigned addr)
{
    asm volatile("ldmatrix.sync.aligned.m8n8.x4.shared.b16 {%0,%1,%2,%3}, [%4];"
                 : "=r"(r0), "=r"(r1), "=r"(r2), "=r"(r3) : "r"(addr));
}

__device__ __forceinline__ void ldsm_x4_t(
    unsigned& r0, unsigned& r1, unsigned& r2, unsigned& r3, unsigned addr)
{
    asm volatile("ldmatrix.sync.aligned.m8n8.x4.trans.shared.b16 {%0,%1,%2,%3}, [%4];"
                 : "=r"(r0), "=r"(r1), "=r"(r2), "=r"(r3) : "r"(addr));
}

// ---------------------------------------------------------------------------
// fp16 tensor-core GEMM, double-buffered, ldmatrix fragments.
// Block 128x256, BK=16, 256 threads = 8 warps (2x4), warp tile 64x64.
// fp32 accum; blockIdx.z selects operand set (merged K/V projection launch).
// ---------------------------------------------------------------------------
constexpr int ASTR = 40;                 // halves
constexpr int BSTR = 264;                // halves
constexpr int ASZH = 128 * ASTR;         // 5120 halves / stage
constexpr int BSZH = 16 * BSTR;          // 4224 halves / stage

__global__ __launch_bounds__(256, 1) void gemm_tc(
    const float* __restrict__ A0, const float* __restrict__ W0,
    const float* __restrict__ bias0, float* __restrict__ C0,
    const float* __restrict__ A1, const float* __restrict__ W1p,
    const float* __restrict__ bias1, float* __restrict__ C1,
    int M, int N, int K, int relu)
{
    __shared__ alignas(16) __half As[2 * ASZH];
    __shared__ alignas(16) __half Bs[2 * BSZH];

    const float* A    = blockIdx.z ? A1    : A0;
    const float* W    = blockIdx.z ? W1p   : W0;
    const float* bias = blockIdx.z ? bias1 : bias0;
    float*       C    = blockIdx.z ? C1    : C0;

    const int tid  = threadIdx.x;
    const int lane = tid & 31;
    const int warp = tid >> 5;
    const int wm   = warp >> 2;
    const int wn   = warp & 3;
    const int g    = lane >> 2;
    const int t4   = lane & 3;
    const int mrow = wm * 64;
    const int nb   = wn * 64;

    const int bm = blockIdx.y * 128;
    const int bn = blockIdx.x * 256;
    const int nk = K >> 4;

    const unsigned As_u32 = (unsigned)__cvta_generic_to_shared(As);
    const unsigned Bs_u32 = (unsigned)__cvta_generic_to_shared(Bs);

    const int mat  = lane >> 3;
    const int mrw  = lane & 7;
    const int arow = (mat & 1) * 8 + mrw;
    const int acol = (mat >> 1) * 8;
    const int aidx[4] = {
        (mrow + 0 * 16 + arow) * ASTR + acol,
        (mrow + 1 * 16 + arow) * ASTR + acol,
        (mrow + 2 * 16 + arow) * ASTR + acol,
        (mrow + 3 * 16 + arow) * ASTR + acol };
    const int krow = (mat & 1) * 8 + mrw;
    const int ncol = (mat >> 1) * 8;
    const int bidx[4] = {
        krow * BSTR + nb + 0 * 16 + ncol,
        krow * BSTR + nb + 1 * 16 + ncol,
        krow * BSTR + nb + 2 * 16 + ncol,
        krow * BSTR + nb + 3 * 16 + ncol };

    float acc[4][8][4];
    #pragma unroll
    for (int mt = 0; mt < 4; mt++)
        #pragma unroll
        for (int nt = 0; nt < 8; nt++)
            #pragma unroll
            for (int i = 0; i < 4; i++) acc[mt][nt][i] = 0.f;

    {
        #pragma unroll
        for (int i = 0; i < 2; i++) {
            const int f  = tid + (i << 8);
            const int m  = f >> 2;
            const int kq = (f & 3) << 2;
            const float4 v = *(const float4*)&A[(size_t)(bm + m) * K + kq];
            uint2 p; p.x = pack_h2(v.x, v.y); p.y = pack_h2(v.z, v.w);
            *(uint2*)(As + m * ASTR + kq) = p;
        }
        #pragma unroll
        for (int i = 0; i < 4; i++) {
            const int f  = tid + (i << 8);
            const int kk = f >> 6;
            const int n  = (f & 63) << 2;
            const float4 u = *(const float4*)&W[(size_t)kk * N + bn + n];
            uint2 p; p.x = pack_h2(u.x, u.y); p.y = pack_h2(u.z, u.w);
            *(uint2*)(Bs + kk * BSTR + n) = p;
        }
    }
    __syncthreads();

    for (int kt = 0; kt < nk; kt++) {
        const int cur = kt & 1;
        const bool pf = (kt + 1 < nk);
        float4 av[2], bv[4];
        if (pf) {
            const int k0n = (kt + 1) << 4;
            #pragma unroll
            for (int i = 0; i < 2; i++) {
                const int f = tid + (i << 8);
                av[i] = *(const float4*)&A[(size_t)(bm + (f >> 2)) * K + k0n + ((f & 3) << 2)];
            }
            #pragma unroll
            for (int i = 0; i < 4; i++) {
                const int f = tid + (i << 8);
                bv[i] = *(const float4*)&W[(size_t)(k0n + (f >> 6)) * N + bn + ((f & 63) << 2)];
            }
        }

        const unsigned abase = As_u32 + (cur * ASZH) * 2;
        const unsigned bbase = Bs_u32 + (cur * BSZH) * 2;
        unsigned a[4][4], bq[4][4];
        #pragma unroll
        for (int mt = 0; mt < 4; mt++)
            ldsm_x4(a[mt][0], a[mt][1], a[mt][2], a[mt][3], abase + aidx[mt] * 2);
        #pragma unroll
        for (int pr = 0; pr < 4; pr++)
            ldsm_x4_t(bq[pr][0], bq[pr][1], bq[pr][2], bq[pr][3], bbase + bidx[pr] * 2);

        #pragma unroll
        for (int mt = 0; mt < 4; mt++)
            #pragma unroll
            for (int nt = 0; nt < 8; nt++) {
                const int pr = nt >> 1, sel = (nt & 1) << 1;
                mma_f16(acc[mt][nt][0], acc[mt][nt][1], acc[mt][nt][2], acc[mt][nt][3],
                        a[mt][0], a[mt][1], a[mt][2], a[mt][3],
                        bq[pr][sel], bq[pr][sel + 1]);
            }

        if (pf) {
            __half* Asn = As + (cur ^ 1) * ASZH;
            __half* Bsn = Bs + (cur ^ 1) * BSZH;
            #pragma unroll
            for (int i = 0; i < 2; i++) {
                const int f  = tid + (i << 8);
                const int m  = f >> 2;
                const int kq = (f & 3) << 2;
                uint2 p; p.x = pack_h2(av[i].x, av[i].y); p.y = pack_h2(av[i].z, av[i].w);
                *(uint2*)(Asn + m * ASTR + kq) = p;
            }
            #pragma unroll
            for (int i = 0; i < 4; i++) {
                const int f  = tid + (i << 8);
                const int kk = f >> 6;
                const int n  = (f & 63) << 2;
                uint2 p; p.x = pack_h2(bv[i].x, bv[i].y); p.y = pack_h2(bv[i].z, bv[i].w);
                *(uint2*)(Bsn + kk * BSTR + n) = p;
            }
        }
        __syncthreads();
    }

    #pragma unroll
    for (int mt = 0; mt < 4; mt++) {
        const int r = bm + mrow + mt * 16 + g;
        #pragma unroll
        for (int nt = 0; nt < 8; nt++) {
            const int c = bn + nb + nt * 8 + 2 * t4;
            const float b0 = bias[c], b1 = bias[c + 1];
            float v0 = acc[mt][nt][0] + b0;
            float v1 = acc[mt][nt][1] + b1;
            float v2 = acc[mt][nt][2] + b0;
            float v3 = acc[mt][nt][3] + b1;
            if (relu) {
                v0 = fmaxf(v0, 0.f); v1 = fmaxf(v1, 0.f);
                v2 = fmaxf(v2, 0.f); v3 = fmaxf(v3, 0.f);
            }
            *(float2*)&C[(size_t)r * N + c]       = make_float2(v0, v1);
            *(float2*)&C[(size_t)(r + 8) * N + c] = make_float2(v2, v3);
        }
    }
}

// ---------------------------------------------------------------------------
// fp16 tensor-core flash attention: q-tile 128, warp owns 16 rows x 64 kv.
// m16n8k16 mma via ldmatrix; softmax fp32 in registers (quad shuffles);
// P packed to half at store, warp-private rows (syncwarp only).
// Static smem: Q[128x40] K[64x40] V[64x40] P[128x72] halves = 38912 B.
// ---------------------------------------------------------------------------
constexpr int QSTR = 40;
constexpr int KSTR = 40;
constexpr int VSTR = 40;
constexpr int PSTR = 72;

__global__ __launch_bounds__(256) void attn_tc(
    const float* __restrict__ QK, const float* __restrict__ Vp,
    float* __restrict__ O, int strict)
{
    __shared__ alignas(16) __half Qs[128 * QSTR];
    __shared__ alignas(16) __half Ks[64 * KSTR];
    __shared__ alignas(16) __half Vs[64 * VSTR];
    __shared__ alignas(16) __half Ps[128 * PSTR];

    const int qt = blockIdx.x;
    const int bh = blockIdx.y;
    const int b  = bh >> 3;
    const int h  = bh & 7;
    const int q0 = qt << 7;
    const int t    = threadIdx.x;
    const int lane = t & 31;
    const int warp = t >> 5;
    const int m0   = warp << 4;
    const int g    = lane >> 2;
    const int t4   = lane & 3;
    const int mat  = lane >> 3;
    const int mrw  = lane & 7;
    const int arow = (mat & 1) * 8 + mrw;    // A-frag row-in-16
    const int acol = (mat >> 1) * 8;         // A-frag k col 0/8

    const unsigned Qs_u = (unsigned)__cvta_generic_to_shared(Qs);
    const unsigned Ks_u = (unsigned)__cvta_generic_to_shared(Ks);
    const unsigned Vs_u = (unsigned)__cvta_generic_to_shared(Vs);
    const unsigned Ps_u = (unsigned)__cvta_generic_to_shared(Ps);

    const size_t base = (size_t)(b * S_) * D_ + h * DK_;

    // ---- stage Q (128 x 32), pre-scaled, fp32 -> half
    for (int i = t; i < 1024; i += 256) {
        const int r = i >> 3, c = (i & 7) << 2;
        float4 v = *(const float4*)&QK[base + (size_t)(q0 + r) * D_ + c];
        uint2 p;
        p.x = pack_h2(v.x * SCALE_, v.y * SCALE_);
        p.y = pack_h2(v.z * SCALE_, v.w * SCALE_);
        *(uint2*)(Qs + r * QSTR + c) = p;
    }
    __syncthreads();

    // Q a-frags: 2 k-steps of 16
    unsigned qf[2][4];
    #pragma unroll
    for (int ks = 0; ks < 2; ks++)
        ldsm_x4(qf[ks][0], qf[ks][1], qf[ks][2], qf[ks][3],
                Qs_u + ((m0 + arow) * QSTR + ks * 16 + acol) * 2);

    float acc_o[4][4];
    #pragma unroll
    for (int nt = 0; nt < 4; nt++)
        #pragma unroll
        for (int i = 0; i < 4; i++) acc_o[nt][i] = 0.f;
    float mrowv[2] = { -1e30f, -1e30f };
    float lrow[2] = { 0.f, 0.f };

    const int rg  = q0 + m0 + g - strict;
    const int rg8 = rg + 8;
    const int ktmax = 2 * qt + 1;

    for (int kt = 0; kt <= ktmax; kt++) {
        const int k0 = kt << 6;
        __syncthreads();
        for (int i = t; i < 512; i += 256) {
            const int rr = i >> 3, c = (i & 7) << 2;
            float4 kv = *(const float4*)&QK[base + (size_t)(k0 + rr) * D_ + c];
            uint2 pk; pk.x = pack_h2(kv.x, kv.y); pk.y = pack_h2(kv.z, kv.w);
            *(uint2*)(Ks + rr * KSTR + c) = pk;
            float4 vv = *(const float4*)&Vp[base + (size_t)(k0 + rr) * D_ + c];
            uint2 pv; pv.x = pack_h2(vv.x, vv.y); pv.y = pack_h2(vv.z, vv.w);
            *(uint2*)(Vs + rr * VSTR + c) = pv;
        }
        __syncthreads();

        // ---- scores: warp 16 x 64 via m16n8k16
        float s[8][4];
        #pragma unroll
        for (int nt = 0; nt < 8; nt++)
            #pragma unroll
            for (int i = 0; i < 4; i++) s[nt][i] = 0.f;
        #pragma unroll
        for (int ks = 0; ks < 2; ks++) {
            const int kb = ks * 16;
            #pragma unroll
            for (int np = 0; np < 4; np++) {
                unsigned bq0, bq1, bq2, bq3;
                // K stored [n][k]: non-trans ldmatrix gives col-major B frag
                ldsm_x4(bq0, bq1, bq2, bq3,
                        Ks_u + ((np * 16 + (mat >> 1) * 8 + mrw) * KSTR + kb + (mat & 1) * 8) * 2);
                mma_f16(s[np*2][0], s[np*2][1], s[np*2][2], s[np*2][3],
                        qf[ks][0], qf[ks][1], qf[ks][2], qf[ks][3], bq0, bq1);
                mma_f16(s[np*2+1][0], s[np*2+1][1], s[np*2+1][2], s[np*2+1][3],
                        qf[ks][0], qf[ks][1], qf[ks][2], qf[ks][3], bq2, bq3);
            }
        }

        // ---- mask (register)
        #pragma unroll
        for (int nt = 0; nt < 8; nt++) {
            const int c0c = k0 + nt * 8 + 2 * t4;
            const int c1c = c0c + 1;
            s[nt][0] = (c0c <= rg ) ? s[nt][0] : -1e30f;
            s[nt][1] = (c1c <= rg ) ? s[nt][1] : -1e30f;
            s[nt][2] = (c0c <= rg8) ? s[nt][2] : -1e30f;
            s[nt][3] = (c1c <= rg8) ? s[nt][3] : -1e30f;
        }

        // ---- row max (register + quad shuffle)
        float mx0 = -1e30f, mx1 = -1e30f;
        #pragma unroll
        for (int nt = 0; nt < 8; nt++) {
            mx0 = fmaxf(mx0, fmaxf(s[nt][0], s[nt][1]));
            mx1 = fmaxf(mx1, fmaxf(s[nt][2], s[nt][3]));
        }
        mx0 = fmaxf(mx0, __shfl_xor_sync(0xffffffffu, mx0, 1));
        mx0 = fmaxf(mx0, __shfl_xor_sync(0xffffffffu, mx0, 2));
        mx1 = fmaxf(mx1, __shfl_xor_sync(0xffffffffu, mx1, 1));
        mx1 = fmaxf(mx1, __shfl_xor_sync(0xffffffffu, mx1, 2));
        const float nm0 = fmaxf(mrowv[0], mx0);
        const float nm1 = fmaxf(mrowv[1], mx1);
        const float cr0 = __expf(mrowv[0] - nm0);
        const float cr1 = __expf(mrowv[1] - nm1);

        // ---- exp + pack P to half, store to warp-private smem rows
        float ps0 = 0.f, ps1 = 0.f;
        #pragma unroll
        for (int nt = 0; nt < 8; nt++) {
            const float p0 = (s[nt][0] > -1e29f) ? __expf(s[nt][0] - nm0) : 0.f;
            const float p1 = (s[nt][1] > -1e29f) ? __expf(s[nt][1] - nm0) : 0.f;
            const float p2 = (s[nt][2] > -1e29f) ? __expf(s[nt][2] - nm1) : 0.f;
            const float p3 = (s[nt][3] > -1e29f) ? __expf(s[nt][3] - nm1) : 0.f;
            ps0 += p0 + p1;
            ps1 += p2 + p3;
            const int cl = nt * 8 + 2 * t4;
            *(unsigned*)(Ps + (m0 + g) * PSTR + cl)     = pack_h2(p0, p1);
            *(unsigned*)(Ps + (m0 + g + 8) * PSTR + cl) = pack_h2(p2, p3);
        }
        ps0 += __shfl_xor_sync(0xffffffffu, ps0, 1);
        ps0 += __shfl_xor_sync(0xffffffffu, ps0, 2);
        ps1 += __shfl_xor_sync(0xffffffffu, ps1, 1);
        ps1 += __shfl_xor_sync(0xffffffffu, ps1, 2);
        lrow[0] = lrow[0] * cr0 + ps0;
        lrow[1] = lrow[1] * cr1 + ps1;
        mrowv[0] = nm0;
        mrowv[1] = nm1;
        __syncwarp();

        // ---- rescale accumulators, then PV via m16n8k16
        #pragma unroll
        for (int nt = 0; nt < 4; nt++) {
            acc_o[nt][0] *= cr0; acc_o[nt][1] *= cr0;
            acc_o[nt][2] *= cr1; acc_o[nt][3] *= cr1;
        }
        #pragma unroll
        for (int ks = 0; ks < 4; ks++) {
            const int kb = ks * 16;
            unsigned pa0, pa1, pa2, pa3;
            ldsm_x4(pa0, pa1, pa2, pa3,
                    Ps_u + ((m0 + arow) * PSTR + kb + acol) * 2);
            #pragma unroll
            for (int np = 0; np < 2; np++) {
                unsigned vb0, vb1, vb2, vb3;
                // V stored [k][n]: trans ldmatrix gives col-major B frag
                ldsm_x4_t(vb0, vb1, vb2, vb3,
                          Vs_u + ((kb + (mat & 1) * 8 + mrw) * VSTR + np * 16 + (mat >> 1) * 8) * 2);
                mma_f16(acc_o[np*2][0], acc_o[np*2][1], acc_o[np*2][2], acc_o[np*2][3],
                        pa0, pa1, pa2, pa3, vb0, vb1);
                mma_f16(acc_o[np*2+1][0], acc_o[np*2+1][1], acc_o[np*2+1][2], acc_o[np*2+1][3],
                        pa0, pa1, pa2, pa3, vb2, vb3);
            }
        }
    }

    // ---- finalize: divide by l (fully-masked row -> 0), write out
    const float i0 = (lrow[0] > 0.f) ? 1.f / lrow[0] : 0.f;
    const float i1 = (lrow[1] > 0.f) ? 1.f / lrow[1] : 0.f;
    const int row = q0 + m0 + g;
    #pragma unroll
    for (int nt = 0; nt < 4; nt++) {
        const int c = nt * 8 + 2 * t4;
        *(float2*)&O[base + (size_t)row * D_ + c] =
            make_float2(acc_o[nt][0] * i0, acc_o[nt][1] * i0);
        *(float2*)&O[base + (size_t)(row + 8) * D_ + c] =
            make_float2(acc_o[nt][2] * i1, acc_o[nt][3] * i1);
    }
}

// ---------------------------------------------------------------------------
// Fused residual add + LayerNorm: warp-per-row (256 floats, 8 per lane).
// ---------------------------------------------------------------------------
__global__ __launch_bounds__(256) void add_ln_kernel(
    const float* __restrict__ X, const float* __restrict__ R,
    const float* __restrict__ gam, const float* __restrict__ bet,
    float* __restrict__ O)
{
    const int warp = threadIdx.x >> 5;
    const int lane = threadIdx.x & 31;
    const int row  = blockIdx.x * 8 + warp;
    const size_t off = (size_t)row * D_ + lane * 8;

    float4 x0 = *(const float4*)&X[off];
    float4 x1 = *(const float4*)&X[off + 4];
    float4 r0 = *(const float4*)&R[off];
    float4 r1 = *(const float4*)&R[off + 4];
    float v[8] = { x0.x + r0.x, x0.y + r0.y, x0.z + r0.z, x0.w + r0.w,
                   x1.x + r1.x, x1.y + r1.y, x1.z + r1.z, x1.w + r1.w };

    float s = 0.f;
    #pragma unroll
    for (int i = 0; i < 8; i++) s += v[i];
    #pragma unroll
    for (int o = 16; o > 0; o >>= 1) s += __shfl_xor_sync(0xffffffffu, s, o);
    const float mu = s * (1.f / 256.f);

    float s2 = 0.f;
    #pragma unroll
    for (int i = 0; i < 8; i++) { v[i] -= mu; s2 += v[i] * v[i]; }
    #pragma unroll
    for (int o = 16; o > 0; o >>= 1) s2 += __shfl_xor_sync(0xffffffffu, s2, o);
    const float rs = rsqrtf(s2 * (1.f / 256.f) + 1e-5f);

    const int c = lane * 8;
    float4 ga = *(const float4*)&gam[c];
    float4 gb = *(const float4*)&gam[c + 4];
    float4 ba = *(const float4*)&bet[c];
    float4 bb = *(const float4*)&bet[c + 4];

    float4 oa = make_float4(v[0] * rs * ga.x + ba.x, v[1] * rs * ga.y + ba.y,
                            v[2] * rs * ga.z + ba.z, v[3] * rs * ga.w + ba.w);
    float4 ob = make_float4(v[4] * rs * gb.x + bb.x, v[5] * rs * gb.y + bb.y,
                            v[6] * rs * gb.z + bb.z, v[7] * rs * gb.w + bb.w);
    *(float4*)&O[off]     = oa;
    *(float4*)&O[off + 4] = ob;
}

// ---------------------------------------------------------------------------
// Host-side orchestration
// ---------------------------------------------------------------------------
struct Scratch { float *y, *x, *kp, *vp, *att, *o, *x1, *f, *h; };

static void launch_layer(const float* Qin, const float* Vin, float* Out,
                         int li, int strict, int apply_pos,
                         void* const* d_in, const Scratch& P)
{
    const float* Wk  = (const float*)d_in[2]  + (size_t)li * D_ * D_;
    const float* bk  = (const float*)d_in[3]  + (size_t)li * D_;
    const float* Wv  = (const float*)d_in[4]  + (size_t)li * D_ * D_;
    const float* bv  = (const float*)d_in[5]  + (size_t)li * D_;
    const float* Wo  = (const float*)d_in[6]  + (size_t)li * D_ * D_;
    const float* bo  = (const float*)d_in[7]  + (size_t)li * D_;
    const float* g1  = (const float*)d_in[8]  + (size_t)li * D_;
    const float* be1 = (const float*)d_in[9]  + (size_t)li * D_;
    const float* W1  = (const float*)d_in[10] + (size_t)li * D_ * DFF_;
    const float* bf1 = (const float*)d_in[11] + (size_t)li * DFF_;
    const float* W2  = (const float*)d_in[12] + (size_t)li * DFF_ * D_;
    const float* bf2 = (const float*)d_in[13] + (size_t)li * D_;
    const float* g2  = (const float*)d_in[14] + (size_t)li * D_;
    const float* be2 = (const float*)d_in[15] + (size_t)li * D_;

    // merged K-proj (set0) + V-proj (set1) via blockIdx.z
    gemm_tc<<<dim3(D_ / 256, BS_ / 128, 2), 256>>>(
        Qin, Wk, bk, P.kp, Vin, Wv, bv, P.vp, BS_, D_, D_, 0);
    attn_tc<<<dim3(S_ / 128, B_ * H_), 256>>>(P.kp, P.vp, P.att, strict);
    gemm_tc<<<dim3(D_ / 256, BS_ / 128, 1), 256>>>(
        P.att, Wo, bo, P.o, P.att, Wo, bo, P.o, BS_, D_, D_, 0);

    float* ln1out = apply_pos ? P.x1 : Out;
    add_ln_kernel<<<BS_ / 8, 256>>>(Qin, P.o, g1, be1, ln1out);

    if (apply_pos) {
        gemm_tc<<<dim3(DFF_ / 256, BS_ / 128, 1), 256>>>(
            P.x1, W1, bf1, P.h, P.x1, W1, bf1, P.h, BS_, DFF_, D_, 1);
        gemm_tc<<<dim3(D_ / 256, BS_ / 128, 1), 256>>>(
            P.h, W2, bf2, P.f, P.h, W2, bf2, P.f, BS_, D_, DFF_, 0);
        add_ln_kernel<<<BS_ / 8, 256>>>(P.x1, P.f, g2, be2, Out);
    }
}

extern "C" void kernel_launch(void* const* d_in, const int* in_sizes, int n_in,
                              void* d_out, int out_size)
{
    (void)in_sizes; (void)n_in; (void)out_size;
    const float* qe = (const float*)d_in[0];   // q_embed_data  -> x stream
    const float* qa = (const float*)d_in[1];   // qa_embed_data -> y stream

    Scratch P;
    cudaGetSymbolAddress((void**)&P.y,  g_y);
    cudaGetSymbolAddress((void**)&P.x,  g_x);
    cudaGetSymbolAddress((void**)&P.kp, g_kp);
    cudaGetSymbolAddress((void**)&P.vp, g_vp);
    cudaGetSymbolAddress((void**)&P.att, g_att);
    cudaGetSymbolAddress((void**)&P.o,  g_o);
    cudaGetSymbolAddress((void**)&P.x1, g_x1);
    cudaGetSymbolAddress((void**)&P.f,  g_f);
    cudaGetSymbolAddress((void**)&P.h,  g_h);

    // Encoder blocks (y = qa stream), mask incl. diagonal, with FFN
    launch_layer(qa,  qa,  P.y, 0, /*strict=*/0, /*apply_pos=*/1, d_in, P);
    launch_layer(P.y, P.y, P.y, 1, 0, 1, d_in, P);

    // Decoder blocks on x stream
    launch_layer(qe,  qe,  P.x, 2, /*strict=*/0, /*apply_pos=*/0, d_in, P);   // self, no FFN
    launch_layer(P.x, P.y, P.x, 3, /*strict=*/1, /*apply_pos=*/1, d_in, P);   // cross (V=y)
    launch_layer(P.x, P.x, P.x, 4, 0, 0, d_in, P);                            // self, no FFN
    launch_layer(P.x, P.y, (float*)d_out, 5, 1, 1, d_in, P);                  // cross -> out
}

// round 11
// speedup vs baseline: 2.0321x; 1.0022x over previous
#include <cuda_runtime.h>
#include <cuda_fp16.h>
#include <math.h>

// Problem dims (fixed by the reference)
constexpr int B_   = 64;
constexpr int S_   = 512;
constexpr int D_   = 256;
constexpr int H_   = 8;
constexpr int DK_  = 32;
constexpr int DFF_ = 1024;
constexpr int BS_  = B_ * S_;          // 32768 rows
constexpr float SCALE_ = 0.17677669529663687f; // 1/sqrt(32)

// ---------------------------------------------------------------------------
// Scratch (no allocations allowed -> __device__ globals)
// ---------------------------------------------------------------------------
__device__ float g_y  [BS_ * D_];
__device__ float g_x  [BS_ * D_];
__device__ float g_kp [BS_ * D_];
__device__ float g_vp [BS_ * D_];
__device__ float g_att[BS_ * D_];
__device__ float g_o  [BS_ * D_];
__device__ float g_x1 [BS_ * D_];
__device__ float g_f  [BS_ * D_];
__device__ float g_h  [BS_ * DFF_];

// ---------------------------------------------------------------------------
// helpers
// ---------------------------------------------------------------------------
__device__ __forceinline__ unsigned pack_h2(float lo, float hi) {
    unsigned u;
    asm("cvt.rn.f16x2.f32 %0, %1, %2;" : "=r"(u) : "f"(hi), "f"(lo));
    return u;
}

__device__ __forceinline__ void mma_f16(
    float& c0, float& c1, float& c2, float& c3,
    unsigned a0, unsigned a1, unsigned a2, unsigned a3,
    unsigned b0, unsigned b1)
{
    asm volatile(
        "mma.sync.aligned.m16n8k16.row.col.f32.f16.f16.f32 "
        "{%0,%1,%2,%3}, {%4,%5,%6,%7}, {%8,%9}, {%0,%1,%2,%3};\n"
        : "+f"(c0), "+f"(c1), "+f"(c2), "+f"(c3)
        : "r"(a0), "r"(a1), "r"(a2), "r"(a3), "r"(b0), "r"(b1));
}

__device__ __forceinline__ void ldsm_x4(
    unsigned& r0, unsigned& r1, unsigned& r2, unsigned& r3, unsigned addr)
{
    asm volatile("ldmatrix.sync.aligned.m8n8.x4.shared.b16 {%0,%1,%2,%3}, [%4];"
                 : "=r"(r0), "=r"(r1), "=r"(r2), "=r"(r3) : "r"(addr));
}

__device__ __forceinline__ void ldsm_x4_t(
    unsigned& r0, unsigned& r1, unsigned& r2, unsigned& r3, unsigned addr)
{
    asm volatile("ldmatrix.sync.aligned.m8n8.x4.trans.shared.b16 {%0,%1,%2,%3}, [%4];"
                 : "=r"(r0), "=r"(r1), "=r"(r2), "=r"(r3) : "r"(addr));
}

// ---------------------------------------------------------------------------
// fp16 tensor-core GEMM, double-buffered, ldmatrix fragments.
// Block 128x256, BK=16, 256 threads = 8 warps (2x4), warp tile 64x64.
// fp32 accum; blockIdx.z selects operand set (merged K/V projection launch).
// ---------------------------------------------------------------------------
constexpr int ASTR = 40;                 // halves
constexpr int BSTR = 264;                // halves
constexpr int ASZH = 128 * ASTR;         // 5120 halves / stage
constexpr int BSZH = 16 * BSTR;          // 4224 halves / stage

__global__ __launch_bounds__(256, 1) void gemm_tc(
    const float* __restrict__ A0, const float* __restrict__ W0,
    const float* __restrict__ bias0, float* __restrict__ C0,
    const float* __restrict__ A1, const float* __restrict__ W1p,
    const float* __restrict__ bias1, float* __restrict__ C1,
    int M, int N, int K, int relu)
{
    __shared__ alignas(16) __half As[2 * ASZH];
    __shared__ alignas(16) __half Bs[2 * BSZH];

    const float* A    = blockIdx.z ? A1    : A0;
    const float* W    = blockIdx.z ? W1p   : W0;
    const float* bias = blockIdx.z ? bias1 : bias0;
    float*       C    = blockIdx.z ? C1    : C0;

    const int tid  = threadIdx.x;
    const int lane = tid & 31;
    const int warp = tid >> 5;
    const int wm   = warp >> 2;
    const int wn   = warp & 3;
    const int g    = lane >> 2;
    const int t4   = lane & 3;
    const int mrow = wm * 64;
    const int nb   = wn * 64;

    const int bm = blockIdx.y * 128;
    const int bn = blockIdx.x * 256;
    const int nk = K >> 4;

    const unsigned As_u32 = (unsigned)__cvta_generic_to_shared(As);
    const unsigned Bs_u32 = (unsigned)__cvta_generic_to_shared(Bs);

    const int mat  = lane >> 3;
    const int mrw  = lane & 7;
    const int arow = (mat & 1) * 8 + mrw;
    const int acol = (mat >> 1) * 8;
    const int aidx[4] = {
        (mrow + 0 * 16 + arow) * ASTR + acol,
        (mrow + 1 * 16 + arow) * ASTR + acol,
        (mrow + 2 * 16 + arow) * ASTR + acol,
        (mrow + 3 * 16 + arow) * ASTR + acol };
    const int krow = (mat & 1) * 8 + mrw;
    const int ncol = (mat >> 1) * 8;
    const int bidx[4] = {
        krow * BSTR + nb + 0 * 16 + ncol,
        krow * BSTR + nb + 1 * 16 + ncol,
        krow * BSTR + nb + 2 * 16 + ncol,
        krow * BSTR + nb + 3 * 16 + ncol };

    float acc[4][8][4];
    #pragma unroll
    for (int mt = 0; mt < 4; mt++)
        #pragma unroll
        for (int nt = 0; nt < 8; nt++)
            #pragma unroll
            for (int i = 0; i < 4; i++) acc[mt][nt][i] = 0.f;

    {
        #pragma unroll
        for (int i = 0; i < 2; i++) {
            const int f  = tid + (i << 8);
            const int m  = f >> 2;
            const int kq = (f & 3) << 2;
            const float4 v = *(const float4*)&A[(size_t)(bm + m) * K + kq];
            uint2 p; p.x = pack_h2(v.x, v.y); p.y = pack_h2(v.z, v.w);
            *(uint2*)(As + m * ASTR + kq) = p;
        }
        #pragma unroll
        for (int i = 0; i < 4; i++) {
            const int f  = tid + (i << 8);
            const int kk = f >> 6;
            const int n  = (f & 63) << 2;
            const float4 u = *(const float4*)&W[(size_t)kk * N + bn + n];
            uint2 p; p.x = pack_h2(u.x, u.y); p.y = pack_h2(u.z, u.w);
            *(uint2*)(Bs + kk * BSTR + n) = p;
        }
    }
    __syncthreads();

    for (int kt = 0; kt < nk; kt++) {
        const int cur = kt & 1;
        const bool pf = (kt + 1 < nk);
        float4 av[2], bv[4];
        if (pf) {
            const int k0n = (kt + 1) << 4;
            #pragma unroll
            for (int i = 0; i < 2; i++) {
                const int f = tid + (i << 8);
                av[i] = *(const float4*)&A[(size_t)(bm + (f >> 2)) * K + k0n + ((f & 3) << 2)];
            }
            #pragma unroll
            for (int i = 0; i < 4; i++) {
                const int f = tid + (i << 8);
                bv[i] = *(const float4*)&W[(size_t)(k0n + (f >> 6)) * N + bn + ((f & 63) << 2)];
            }
        }

        const unsigned abase = As_u32 + (cur * ASZH) * 2;
        const unsigned bbase = Bs_u32 + (cur * BSZH) * 2;
        unsigned a[4][4], bq[4][4];
        #pragma unroll
        for (int mt = 0; mt < 4; mt++)
            ldsm_x4(a[mt][0], a[mt][1], a[mt][2], a[mt][3], abase + aidx[mt] * 2);
        #pragma unroll
        for (int pr = 0; pr < 4; pr++)
            ldsm_x4_t(bq[pr][0], bq[pr][1], bq[pr][2], bq[pr][3], bbase + bidx[pr] * 2);

        #pragma unroll
        for (int mt = 0; mt < 4; mt++)
            #pragma unroll
            for (int nt = 0; nt < 8; nt++) {
                const int pr = nt >> 1, sel = (nt & 1) << 1;
                mma_f16(acc[mt][nt][0], acc[mt][nt][1], acc[mt][nt][2], acc[mt][nt][3],
                        a[mt][0], a[mt][1], a[mt][2], a[mt][3],
                        bq[pr][sel], bq[pr][sel + 1]);
            }

        if (pf) {
            __half* Asn = As + (cur ^ 1) * ASZH;
            __half* Bsn = Bs + (cur ^ 1) * BSZH;
            #pragma unroll
            for (int i = 0; i < 2; i++) {
                const int f  = tid + (i << 8);
                const int m  = f >> 2;
                const int kq = (f & 3) << 2;
                uint2 p; p.x = pack_h2(av[i].x, av[i].y); p.y = pack_h2(av[i].z, av[i].w);
                *(uint2*)(Asn + m * ASTR + kq) = p;
            }
            #pragma unroll
            for (int i = 0; i < 4; i++) {
                const int f  = tid + (i << 8);
                const int kk = f >> 6;
                const int n  = (f & 63) << 2;
                uint2 p; p.x = pack_h2(bv[i].x, bv[i].y); p.y = pack_h2(bv[i].z, bv[i].w);
                *(uint2*)(Bsn + kk * BSTR + n) = p;
            }
        }
        __syncthreads();
    }

    #pragma unroll
    for (int mt = 0; mt < 4; mt++) {
        const int r = bm + mrow + mt * 16 + g;
        #pragma unroll
        for (int nt = 0; nt < 8; nt++) {
            const int c = bn + nb + nt * 8 + 2 * t4;
            const float b0 = bias[c], b1 = bias[c + 1];
            float v0 = acc[mt][nt][0] + b0;
            float v1 = acc[mt][nt][1] + b1;
            float v2 = acc[mt][nt][2] + b0;
            float v3 = acc[mt][nt][3] + b1;
            if (relu) {
                v0 = fmaxf(v0, 0.f); v1 = fmaxf(v1, 0.f);
                v2 = fmaxf(v2, 0.f); v3 = fmaxf(v3, 0.f);
            }
            *(float2*)&C[(size_t)r * N + c]       = make_float2(v0, v1);
            *(float2*)&C[(size_t)(r + 8) * N + c] = make_float2(v2, v3);
        }
    }
}

// ---------------------------------------------------------------------------
// fp16 tensor-core flash attention: q-tile 128, warp owns 16 rows x 64 kv.
// m16n8k16 mma via ldmatrix; softmax fp32 in registers (quad shuffles);
// P packed to half at store, warp-private rows (syncwarp only).
// Static smem: Q[128x40] K[64x40] V[64x40] P[128x72] halves = 38912 B.
// ---------------------------------------------------------------------------
constexpr int QSTR = 40;
constexpr int KSTR = 40;
constexpr int VSTR = 40;
constexpr int PSTR = 72;

__global__ __launch_bounds__(256) void attn_tc(
    const float* __restrict__ QK, const float* __restrict__ Vp,
    float* __restrict__ O, int strict)
{
    __shared__ alignas(16) __half Qs[128 * QSTR];
    __shared__ alignas(16) __half Ks[64 * KSTR];
    __shared__ alignas(16) __half Vs[64 * VSTR];
    __shared__ alignas(16) __half Ps[128 * PSTR];

    const int qt = blockIdx.x;
    const int bh = blockIdx.y;
    const int b  = bh >> 3;
    const int h  = bh & 7;
    const int q0 = qt << 7;
    const int t    = threadIdx.x;
    const int lane = t & 31;
    const int warp = t >> 5;
    const int m0   = warp << 4;
    const int g    = lane >> 2;
    const int t4   = lane & 3;
    const int mat  = lane >> 3;
    const int mrw  = lane & 7;
    const int arow = (mat & 1) * 8 + mrw;    // A-frag row-in-16
    const int acol = (mat >> 1) * 8;         // A-frag k col 0/8

    const unsigned Qs_u = (unsigned)__cvta_generic_to_shared(Qs);
    const unsigned Ks_u = (unsigned)__cvta_generic_to_shared(Ks);
    const unsigned Vs_u = (unsigned)__cvta_generic_to_shared(Vs);
    const unsigned Ps_u = (unsigned)__cvta_generic_to_shared(Ps);

    const size_t base = (size_t)(b * S_) * D_ + h * DK_;

    // ---- stage Q (128 x 32), pre-scaled, fp32 -> half
    for (int i = t; i < 1024; i += 256) {
        const int r = i >> 3, c = (i & 7) << 2;
        float4 v = *(const float4*)&QK[base + (size_t)(q0 + r) * D_ + c];
        uint2 p;
        p.x = pack_h2(v.x * SCALE_, v.y * SCALE_);
        p.y = pack_h2(v.z * SCALE_, v.w * SCALE_);
        *(uint2*)(Qs + r * QSTR + c) = p;
    }
    __syncthreads();

    // Q a-frags: 2 k-steps of 16
    unsigned qf[2][4];
    #pragma unroll
    for (int ks = 0; ks < 2; ks++)
        ldsm_x4(qf[ks][0], qf[ks][1], qf[ks][2], qf[ks][3],
                Qs_u + ((m0 + arow) * QSTR + ks * 16 + acol) * 2);

    float acc_o[4][4];
    #pragma unroll
    for (int nt = 0; nt < 4; nt++)
        #pragma unroll
        for (int i = 0; i < 4; i++) acc_o[nt][i] = 0.f;
    float mrowv[2] = { -1e30f, -1e30f };
    float lrow[2] = { 0.f, 0.f };

    const int rg  = q0 + m0 + g - strict;
    const int rg8 = rg + 8;
    const int ktmax = 2 * qt + 1;

    for (int kt = 0; kt <= ktmax; kt++) {
        const int k0 = kt << 6;
        __syncthreads();
        for (int i = t; i < 512; i += 256) {
            const int rr = i >> 3, c = (i & 7) << 2;
            float4 kv = *(const float4*)&QK[base + (size_t)(k0 + rr) * D_ + c];
            uint2 pk; pk.x = pack_h2(kv.x, kv.y); pk.y = pack_h2(kv.z, kv.w);
            *(uint2*)(Ks + rr * KSTR + c) = pk;
            float4 vv = *(const float4*)&Vp[base + (size_t)(k0 + rr) * D_ + c];
            uint2 pv; pv.x = pack_h2(vv.x, vv.y); pv.y = pack_h2(vv.z, vv.w);
            *(uint2*)(Vs + rr * VSTR + c) = pv;
        }
        __syncthreads();

        // ---- scores: warp 16 x 64 via m16n8k16
        float s[8][4];
        #pragma unroll
        for (int nt = 0; nt < 8; nt++)
            #pragma unroll
            for (int i = 0; i < 4; i++) s[nt][i] = 0.f;
        #pragma unroll
        for (int ks = 0; ks < 2; ks++) {
            const int kb = ks * 16;
            #pragma unroll
            for (int np = 0; np < 4; np++) {
                unsigned bq0, bq1, bq2, bq3;
                // K stored [n][k]: non-trans ldmatrix gives col-major B frag
                ldsm_x4(bq0, bq1, bq2, bq3,
                        Ks_u + ((np * 16 + (mat >> 1) * 8 + mrw) * KSTR + kb + (mat & 1) * 8) * 2);
                mma_f16(s[np*2][0], s[np*2][1], s[np*2][2], s[np*2][3],
                        qf[ks][0], qf[ks][1], qf[ks][2], qf[ks][3], bq0, bq1);
                mma_f16(s[np*2+1][0], s[np*2+1][1], s[np*2+1][2], s[np*2+1][3],
                        qf[ks][0], qf[ks][1], qf[ks][2], qf[ks][3], bq2, bq3);
            }
        }

        // ---- mask (register)
        #pragma unroll
        for (int nt = 0; nt < 8; nt++) {
            const int c0c = k0 + nt * 8 + 2 * t4;
            const int c1c = c0c + 1;
            s[nt][0] = (c0c <= rg ) ? s[nt][0] : -1e30f;
            s[nt][1] = (c1c <= rg ) ? s[nt][1] : -1e30f;
            s[nt][2] = (c0c <= rg8) ? s[nt][2] : -1e30f;
            s[nt][3] = (c1c <= rg8) ? s[nt][3] : -1e30f;
        }

        // ---- row max (register + quad shuffle)
        float mx0 = -1e30f, mx1 = -1e30f;
        #pragma unroll
        for (int nt = 0; nt < 8; nt++) {
            mx0 = fmaxf(mx0, fmaxf(s[nt][0], s[nt][1]));
            mx1 = fmaxf(mx1, fmaxf(s[nt][2], s[nt][3]));
        }
        mx0 = fmaxf(mx0, __shfl_xor_sync(0xffffffffu, mx0, 1));
        mx0 = fmaxf(mx0, __shfl_xor_sync(0xffffffffu, mx0, 2));
        mx1 = fmaxf(mx1, __shfl_xor_sync(0xffffffffu, mx1, 1));
        mx1 = fmaxf(mx1, __shfl_xor_sync(0xffffffffu, mx1, 2));
        const float nm0 = fmaxf(mrowv[0], mx0);
        const float nm1 = fmaxf(mrowv[1], mx1);
        const float cr0 = __expf(mrowv[0] - nm0);
        const float cr1 = __expf(mrowv[1] - nm1);

        // ---- exp + pack P to half, store to warp-private smem rows
        float ps0 = 0.f, ps1 = 0.f;
        #pragma unroll
        for (int nt = 0; nt < 8; nt++) {
            const float p0 = (s[nt][0] > -1e29f) ? __expf(s[nt][0] - nm0) : 0.f;
            const float p1 = (s[nt][1] > -1e29f) ? __expf(s[nt][1] - nm0) : 0.f;
            const float p2 = (s[nt][2] > -1e29f) ? __expf(s[nt][2] - nm1) : 0.f;
            const float p3 = (s[nt][3] > -1e29f) ? __expf(s[nt][3] - nm1) : 0.f;
            ps0 += p0 + p1;
            ps1 += p2 + p3;
            const int cl = nt * 8 + 2 * t4;
            *(unsigned*)(Ps + (m0 + g) * PSTR + cl)     = pack_h2(p0, p1);
            *(unsigned*)(Ps + (m0 + g + 8) * PSTR + cl) = pack_h2(p2, p3);
        }
        ps0 += __shfl_xor_sync(0xffffffffu, ps0, 1);
        ps0 += __shfl_xor_sync(0xffffffffu, ps0, 2);
        ps1 += __shfl_xor_sync(0xffffffffu, ps1, 1);
        ps1 += __shfl_xor_sync(0xffffffffu, ps1, 2);
        lrow[0] = lrow[0] * cr0 + ps0;
        lrow[1] = lrow[1] * cr1 + ps1;
        mrowv[0] = nm0;
        mrowv[1] = nm1;
        __syncwarp();

        // ---- rescale accumulators, then PV via m16n8k16
        #pragma unroll
        for (int nt = 0; nt < 4; nt++) {
            acc_o[nt][0] *= cr0; acc_o[nt][1] *= cr0;
            acc_o[nt][2] *= cr1; acc_o[nt][3] *= cr1;
        }
        #pragma unroll
        for (int ks = 0; ks < 4; ks++) {
            const int kb = ks * 16;
            unsigned pa0, pa1, pa2, pa3;
            ldsm_x4(pa0, pa1, pa2, pa3,
                    Ps_u + ((m0 + arow) * PSTR + kb + acol) * 2);
            #pragma unroll
            for (int np = 0; np < 2; np++) {
                unsigned vb0, vb1, vb2, vb3;
                // V stored [k][n]: trans ldmatrix gives col-major B frag
                ldsm_x4_t(vb0, vb1, vb2, vb3,
                          Vs_u + ((kb + (mat & 1) * 8 + mrw) * VSTR + np * 16 + (mat >> 1) * 8) * 2);
                mma_f16(acc_o[np*2][0], acc_o[np*2][1], acc_o[np*2][2], acc_o[np*2][3],
                        pa0, pa1, pa2, pa3, vb0, vb1);
                mma_f16(acc_o[np*2+1][0], acc_o[np*2+1][1], acc_o[np*2+1][2], acc_o[np*2+1][3],
                        pa0, pa1, pa2, pa3, vb2, vb3);
            }
        }
    }

    // ---- finalize: divide by l (fully-masked row -> 0), write out
    const float i0 = (lrow[0] > 0.f) ? 1.f / lrow[0] : 0.f;
    const float i1 = (lrow[1] > 0.f) ? 1.f / lrow[1] : 0.f;
    const int row = q0 + m0 + g;
    #pragma unroll
    for (int nt = 0; nt < 4; nt++) {
        const int c = nt * 8 + 2 * t4;
        *(float2*)&O[base + (size_t)row * D_ + c] =
            make_float2(acc_o[nt][0] * i0, acc_o[nt][1] * i0);
        *(float2*)&O[base + (size_t)(row + 8) * D_ + c] =
            make_float2(acc_o[nt][2] * i1, acc_o[nt][3] * i1);
    }
}

// ---------------------------------------------------------------------------
// Fused residual add + LayerNorm: warp-per-row (256 floats, 8 per lane).
// ---------------------------------------------------------------------------
__global__ __launch_bounds__(256) void add_ln_kernel(
    const float* __restrict__ X, const float* __restrict__ R,
    const float* __restrict__ gam, const float* __restrict__ bet,
    float* __restrict__ O)
{
    const int warp = threadIdx.x >> 5;
    const int lane = threadIdx.x & 31;
    const int row  = blockIdx.x * 8 + warp;
    const size_t off = (size_t)row * D_ + lane * 8;

    float4 x0 = *(const float4*)&X[off];
    float4 x1 = *(const float4*)&X[off + 4];
    float4 r0 = *(const float4*)&R[off];
    float4 r1 = *(const float4*)&R[off + 4];
    float v[8] = { x0.x + r0.x, x0.y + r0.y, x0.z + r0.z, x0.w + r0.w,
                   x1.x + r1.x, x1.y + r1.y, x1.z + r1.z, x1.w + r1.w };

    float s = 0.f;
    #pragma unroll
    for (int i = 0; i < 8; i++) s += v[i];
    #pragma unroll
    for (int o = 16; o > 0; o >>= 1) s += __shfl_xor_sync(0xffffffffu, s, o);
    const float mu = s * (1.f / 256.f);

    float s2 = 0.f;
    #pragma unroll
    for (int i = 0; i < 8; i++) { v[i] -= mu; s2 += v[i] * v[i]; }
    #pragma unroll
    for (int o = 16; o > 0; o >>= 1) s2 += __shfl_xor_sync(0xffffffffu, s2, o);
    const float rs = rsqrtf(s2 * (1.f / 256.f) + 1e-5f);

    const int c = lane * 8;
    float4 ga = *(const float4*)&gam[c];
    float4 gb = *(const float4*)&gam[c + 4];
    float4 ba = *(const float4*)&bet[c];
    float4 bb = *(const float4*)&bet[c + 4];

    float4 oa = make_float4(v[0] * rs * ga.x + ba.x, v[1] * rs * ga.y + ba.y,
                            v[2] * rs * ga.z + ba.z, v[3] * rs * ga.w + ba.w);
    float4 ob = make_float4(v[4] * rs * gb.x + bb.x, v[5] * rs * gb.y + bb.y,
                            v[6] * rs * gb.z + bb.z, v[7] * rs * gb.w + bb.w);
    *(float4*)&O[off]     = oa;
    *(float4*)&O[off + 4] = ob;
}

// ---------------------------------------------------------------------------
// Host-side orchestration
// ---------------------------------------------------------------------------
struct Scratch { float *y, *x, *kp, *vp, *att, *o, *x1, *f, *h; };

static void launch_layer(const float* Qin, const float* Vin, float* Out,
                         int li, int strict, int apply_pos,
                         void* const* d_in, const Scratch& P)
{
    const float* Wk  = (const float*)d_in[2]  + (size_t)li * D_ * D_;
    const float* bk  = (const float*)d_in[3]  + (size_t)li * D_;
    const float* Wv  = (const float*)d_in[4]  + (size_t)li * D_ * D_;
    const float* bv  = (const float*)d_in[5]  + (size_t)li * D_;
    const float* Wo  = (const float*)d_in[6]  + (size_t)li * D_ * D_;
    const float* bo  = (const float*)d_in[7]  + (size_t)li * D_;
    const float* g1  = (const float*)d_in[8]  + (size_t)li * D_;
    const float* be1 = (const float*)d_in[9]  + (size_t)li * D_;
    const float* W1  = (const float*)d_in[10] + (size_t)li * D_ * DFF_;
    const float* bf1 = (const float*)d_in[11] + (size_t)li * DFF_;
    const float* W2  = (const float*)d_in[12] + (size_t)li * DFF_ * D_;
    const float* bf2 = (const float*)d_in[13] + (size_t)li * D_;
    const float* g2  = (const float*)d_in[14] + (size_t)li * D_;
    const float* be2 = (const float*)d_in[15] + (size_t)li * D_;

    // merged K-proj (set0) + V-proj (set1) via blockIdx.z
    gemm_tc<<<dim3(D_ / 256, BS_ / 128, 2), 256>>>(
        Qin, Wk, bk, P.kp, Vin, Wv, bv, P.vp, BS_, D_, D_, 0);
    attn_tc<<<dim3(S_ / 128, B_ * H_), 256>>>(P.kp, P.vp, P.att, strict);
    gemm_tc<<<dim3(D_ / 256, BS_ / 128, 1), 256>>>(
        P.att, Wo, bo, P.o, P.att, Wo, bo, P.o, BS_, D_, D_, 0);

    float* ln1out = apply_pos ? P.x1 : Out;
    add_ln_kernel<<<BS_ / 8, 256>>>(Qin, P.o, g1, be1, ln1out);

    if (apply_pos) {
        gemm_tc<<<dim3(DFF_ / 256, BS_ / 128, 1), 256>>>(
            P.x1, W1, bf1, P.h, P.x1, W1, bf1, P.h, BS_, DFF_, D_, 1);
        gemm_tc<<<dim3(D_ / 256, BS_ / 128, 1), 256>>>(
            P.h, W2, bf2, P.f, P.h, W2, bf2, P.f, BS_, D_, DFF_, 0);
        add_ln_kernel<<<BS_ / 8, 256>>>(P.x1, P.f, g2, be2, Out);
    }
}

extern "C" void kernel_launch(void* const* d_in, const int* in_sizes, int n_in,
                              void* d_out, int out_size)
{
    (void)in_sizes; (void)n_in; (void)out_size;
    const float* qe = (const float*)d_in[0];   // q_embed_data  -> x stream
    const float* qa = (const float*)d_in[1];   // qa_embed_data -> y stream

    Scratch P;
    cudaGetSymbolAddress((void**)&P.y,  g_y);
    cudaGetSymbolAddress((void**)&P.x,  g_x);
    cudaGetSymbolAddress((void**)&P.kp, g_kp);
    cudaGetSymbolAddress((void**)&P.vp, g_vp);
    cudaGetSymbolAddress((void**)&P.att, g_att);
    cudaGetSymbolAddress((void**)&P.o,  g_o);
    cudaGetSymbolAddress((void**)&P.x1, g_x1);
    cudaGetSymbolAddress((void**)&P.f,  g_f);
    cudaGetSymbolAddress((void**)&P.h,  g_h);

    // Encoder blocks (y = qa stream), mask incl. diagonal, with FFN
    launch_layer(qa,  qa,  P.y, 0, /*strict=*/0, /*apply_pos=*/1, d_in, P);
    launch_layer(P.y, P.y, P.y, 1, 0, 1, d_in, P);

    // Decoder blocks on x stream
    launch_layer(qe,  qe,  P.x, 2, /*strict=*/0, /*apply_pos=*/0, d_in, P);   // self, no FFN
    launch_layer(P.x, P.y, P.x, 3, /*strict=*/1, /*apply_pos=*/1, d_in, P);   // cross (V=y)
    launch_layer(P.x, P.x, P.x, 4, 0, 0, d_in, P);                            // self, no FFN
    launch_layer(P.x, P.y, (float*)d_out, 5, 1, 1, d_in, P);                  // cross -> out
}